// round 3
// baseline (speedup 1.0000x reference)
#include <cuda_runtime.h>
#include <math.h>

// Problem constants
#define NB    2
#define MSEQ  2048
#define DIM   1024
#define NH    16
#define DPH   64
#define TTOK  (NB * MSEQ)      // 4096 tokens
#define DH3   (3 * DIM)        // 3072
#define DEXP  (2 * DIM)        // 2048

// ---------------------------------------------------------------------------
// Scratch (allocation-free: __device__ globals). ~195 MB total.
// ---------------------------------------------------------------------------
__device__ float g_qvk[TTOK * DH3];                         // 50 MB
__device__ float g_Q[NB * NH * MSEQ * DPH];                 // 16 MB [b=n*16+h][m][dph]
__device__ float g_K[NB * NH * MSEQ * DPH];                 // 16 MB
__device__ float g_V[NB * NH * MSEQ * DPH];                 // 16 MB
__device__ float g_att[TTOK * DIM];                         // 16 MB
__device__ float g_t1[TTOK * DIM];                          // 16 MB
__device__ float g_t2[TTOK * DIM];                          // 16 MB
__device__ float g_h1[TTOK * DEXP];                         // 32 MB
__device__ float g_t3[TTOK * DIM];                          // 16 MB

__device__ __forceinline__ float relu6f(float v) {
    return fminf(fmaxf(v, 0.0f), 6.0f);
}

// ---------------------------------------------------------------------------
// Generic SGEMM: C = relu6(A[M,K] @ B[K,N] + bias)
// 128x128 tile, BK=8, 256 threads, 8x8 per-thread microtile.
// outmode 0: C[r*ldc + c]
// outmode 1: QKV head scatter: n=r>>11, m=r&2047, h=c&15, dph=c>>4
//            C[(((n*16+h)*2048 + m)*64) + dph]
// ---------------------------------------------------------------------------
__global__ void __launch_bounds__(256) gemm_relu6(
    const float* __restrict__ A, int lda,
    const float* __restrict__ B, int ldb,
    const float* __restrict__ bias,
    float* __restrict__ C, int ldc,
    int K, int outmode)
{
    __shared__ float As[8][128];
    __shared__ float Bs[8][128];

    const int tid  = threadIdx.x;
    const int row0 = blockIdx.y * 128;
    const int col0 = blockIdx.x * 128;

    const int arow = tid >> 1;            // 0..127
    const int acol = (tid & 1) * 4;       // 0 or 4
    const int brow = tid >> 5;            // 0..7
    const int bcol = (tid & 31) * 4;      // 0..124

    const float* Aptr = A + (size_t)(row0 + arow) * lda + acol;
    const float* Bptr = B + (size_t)brow * ldb + col0 + bcol;

    const int ty = tid >> 4;              // 0..15
    const int tx = tid & 15;              // 0..15

    float acc[8][8];
#pragma unroll
    for (int i = 0; i < 8; i++)
#pragma unroll
        for (int j = 0; j < 8; j++) acc[i][j] = 0.0f;

    for (int k0 = 0; k0 < K; k0 += 8) {
        float4 av = *(const float4*)Aptr;
        float4 bv = *(const float4*)Bptr;
        Aptr += 8;
        Bptr += (size_t)8 * ldb;

        __syncthreads();  // previous iteration's reads complete
        As[acol + 0][arow] = av.x;
        As[acol + 1][arow] = av.y;
        As[acol + 2][arow] = av.z;
        As[acol + 3][arow] = av.w;
        *(float4*)&Bs[brow][bcol] = bv;
        __syncthreads();

#pragma unroll
        for (int kk = 0; kk < 8; kk++) {
            float4 a0 = *(const float4*)&As[kk][ty * 8];
            float4 a1 = *(const float4*)&As[kk][ty * 8 + 4];
            float4 b0 = *(const float4*)&Bs[kk][tx * 8];
            float4 b1 = *(const float4*)&Bs[kk][tx * 8 + 4];
            float a[8] = {a0.x, a0.y, a0.z, a0.w, a1.x, a1.y, a1.z, a1.w};
            float b[8] = {b0.x, b0.y, b0.z, b0.w, b1.x, b1.y, b1.z, b1.w};
#pragma unroll
            for (int i = 0; i < 8; i++)
#pragma unroll
                for (int j = 0; j < 8; j++)
                    acc[i][j] += a[i] * b[j];
        }
    }

#pragma unroll
    for (int i = 0; i < 8; i++) {
        int r = row0 + ty * 8 + i;
#pragma unroll
        for (int j = 0; j < 8; j++) {
            int c = col0 + tx * 8 + j;
            float v = relu6f(acc[i][j] + bias[c]);
            if (outmode == 0) {
                C[(size_t)r * ldc + c] = v;
            } else {
                int n = r >> 11, m = r & 2047;
                int h = c & 15, dph = c >> 4;
                C[((((size_t)(n * 16 + h) * 2048) + m) * 64) + dph] = v;
            }
        }
    }
}

// ---------------------------------------------------------------------------
// Fused flash attention (fp32, head dim 64, no mask).
// Grid: (1, MSEQ/64, NB*NH). Block: 256 threads.
// Dynamic smem: 4 x [64][68] float tiles = 69632 bytes (attribute opt-in).
// Per block: 64 q-rows of one head-batch b = n*16+h.
//   Qs[d][m] resident; loop k-tiles of 64: Ks[d][k], Vs[k][dph];
//   S via 4x4 microtile; online softmax (16-lane shfl row reductions);
//   P staged in Ps[k][m] smem; PV accumulated in registers.
// Output: att[n*MSEQ + q][h*64 + dph].
// ---------------------------------------------------------------------------
#define FA_SMEM_BYTES (4 * 64 * 68 * 4)

__global__ void __launch_bounds__(256) flash_attn(
    const float* __restrict__ Qb, const float* __restrict__ Kb,
    const float* __restrict__ Vb, float* __restrict__ outbuf,
    float invscale)
{
    extern __shared__ float smem[];
    float (*Qs)[68] = (float (*)[68])(smem);                 // [d][m]
    float (*Ks)[68] = (float (*)[68])(smem + 64 * 68);       // [d][k]
    float (*Vs)[68] = (float (*)[68])(smem + 2 * 64 * 68);   // [k][dph]
    float (*Ps)[68] = (float (*)[68])(smem + 3 * 64 * 68);   // [k][m]

    const int b = blockIdx.z;
    const int n = b >> 4, h = b & 15;
    const float* Q  = Qb + (size_t)b * MSEQ * DPH;
    const float* Kp = Kb + (size_t)b * MSEQ * DPH;
    const float* Vp = Vb + (size_t)b * MSEQ * DPH;
    const int q0 = blockIdx.y * 64;

    const int tid = threadIdx.x;
    const int ty = tid >> 4, tx = tid & 15;   // 16x16 thread grid

    // Load Q tile once (transposed to [d][m])
#pragma unroll
    for (int i = 0; i < 4; i++) {
        int f = i * 256 + tid;          // float4 index 0..1023
        int r  = f >> 4;                // row 0..63
        int c4 = (f & 15) * 4;          // col 0..60
        float4 qv = *(const float4*)(Q + (size_t)(q0 + r) * DPH + c4);
        Qs[c4 + 0][r] = qv.x; Qs[c4 + 1][r] = qv.y;
        Qs[c4 + 2][r] = qv.z; Qs[c4 + 3][r] = qv.w;
    }

    float m_run[4], l_run[4];
    float acc[4][4];
#pragma unroll
    for (int i = 0; i < 4; i++) {
        m_run[i] = -3.4e38f;
        l_run[i] = 0.0f;
#pragma unroll
        for (int j = 0; j < 4; j++) acc[i][j] = 0.0f;
    }

    for (int k0 = 0; k0 < MSEQ; k0 += 64) {
        __syncthreads();   // previous iteration's Ks/Vs/Ps reads complete
#pragma unroll
        for (int i = 0; i < 4; i++) {
            int f = i * 256 + tid;
            int r  = f >> 4;
            int c4 = (f & 15) * 4;
            float4 kv = *(const float4*)(Kp + (size_t)(k0 + r) * DPH + c4);
            float4 vv = *(const float4*)(Vp + (size_t)(k0 + r) * DPH + c4);
            Ks[c4 + 0][r] = kv.x; Ks[c4 + 1][r] = kv.y;
            Ks[c4 + 2][r] = kv.z; Ks[c4 + 3][r] = kv.w;
            *(float4*)&Vs[r][c4] = vv;
        }
        __syncthreads();

        // S[i][j] = (Q row ty*4+i) . (K row tx*4+j) * invscale
        float s[4][4];
#pragma unroll
        for (int i = 0; i < 4; i++)
#pragma unroll
            for (int j = 0; j < 4; j++) s[i][j] = 0.0f;

#pragma unroll 8
        for (int d = 0; d < 64; d++) {
            float4 a4 = *(const float4*)&Qs[d][ty * 4];
            float4 b4 = *(const float4*)&Ks[d][tx * 4];
            float a[4] = {a4.x, a4.y, a4.z, a4.w};
            float bb[4] = {b4.x, b4.y, b4.z, b4.w};
#pragma unroll
            for (int i = 0; i < 4; i++)
#pragma unroll
                for (int j = 0; j < 4; j++)
                    s[i][j] += a[i] * bb[j];
        }

        // Online softmax update, per row (reduce across 16 tx lanes)
#pragma unroll
        for (int i = 0; i < 4; i++) {
            float mx = fmaxf(fmaxf(s[i][0] * invscale, s[i][1] * invscale),
                             fmaxf(s[i][2] * invscale, s[i][3] * invscale));
#pragma unroll
            for (int off = 8; off >= 1; off >>= 1)
                mx = fmaxf(mx, __shfl_xor_sync(0xffffffffu, mx, off));
            float m_new = fmaxf(m_run[i], mx);
            float corr = __expf(m_run[i] - m_new);

            float p0 = __expf(s[i][0] * invscale - m_new);
            float p1 = __expf(s[i][1] * invscale - m_new);
            float p2 = __expf(s[i][2] * invscale - m_new);
            float p3 = __expf(s[i][3] * invscale - m_new);
            s[i][0] = p0; s[i][1] = p1; s[i][2] = p2; s[i][3] = p3;

            float rs = p0 + p1 + p2 + p3;
#pragma unroll
            for (int off = 8; off >= 1; off >>= 1)
                rs += __shfl_xor_sync(0xffffffffu, rs, off);

            l_run[i] = l_run[i] * corr + rs;
            m_run[i] = m_new;
#pragma unroll
            for (int j = 0; j < 4; j++) acc[i][j] *= corr;
        }

        // Stage P to smem as [k][m]
#pragma unroll
        for (int i = 0; i < 4; i++)
#pragma unroll
            for (int j = 0; j < 4; j++)
                Ps[tx * 4 + j][ty * 4 + i] = s[i][j];
        __syncthreads();

        // acc[i][j] += sum_k Ps[k][ty*4+i] * Vs[k][tx*4+j]
#pragma unroll 8
        for (int kk = 0; kk < 64; kk++) {
            float4 a4 = *(const float4*)&Ps[kk][ty * 4];
            float4 b4 = *(const float4*)&Vs[kk][tx * 4];
            float a[4] = {a4.x, a4.y, a4.z, a4.w};
            float bb[4] = {b4.x, b4.y, b4.z, b4.w};
#pragma unroll
            for (int i = 0; i < 4; i++)
#pragma unroll
                for (int j = 0; j < 4; j++)
                    acc[i][j] += a[i] * bb[j];
        }
    }

    // Finalize and scatter: att[n*MSEQ + q][h*64 + dph]
#pragma unroll
    for (int i = 0; i < 4; i++) {
        float inv = 1.0f / l_run[i];
        int tok = n * MSEQ + q0 + ty * 4 + i;
#pragma unroll
        for (int j = 0; j < 4; j++) {
            int c = h * 64 + tx * 4 + j;
            outbuf[(size_t)tok * DIM + c] = acc[i][j] * inv;
        }
    }
}

// ---------------------------------------------------------------------------
// LayerNorm over last dim (1024), one block per row.
// ---------------------------------------------------------------------------
__global__ void __launch_bounds__(256) layernorm_rows(
    const float* __restrict__ X, const float* __restrict__ w,
    const float* __restrict__ bb, float* __restrict__ Y)
{
    const int row = blockIdx.x;
    const float* x = X + (size_t)row * DIM;
    float* y = Y + (size_t)row * DIM;
    const int tid = threadIdx.x;

    float v[4];
    float s = 0.0f;
#pragma unroll
    for (int i = 0; i < 4; i++) {
        v[i] = x[i * 256 + tid];
        s += v[i];
    }

    __shared__ float red[256];
    red[tid] = s;
    __syncthreads();
#pragma unroll
    for (int st = 128; st >= 1; st >>= 1) {
        if (tid < st) red[tid] += red[tid + st];
        __syncthreads();
    }
    float mu = red[0] * (1.0f / DIM);
    __syncthreads();

    float vs = 0.0f;
#pragma unroll
    for (int i = 0; i < 4; i++) {
        float d = v[i] - mu;
        vs += d * d;
    }
    red[tid] = vs;
    __syncthreads();
#pragma unroll
    for (int st = 128; st >= 1; st >>= 1) {
        if (tid < st) red[tid] += red[tid + st];
        __syncthreads();
    }
    float var = red[0] * (1.0f / DIM);
    float inv = rsqrtf(var + 1e-5f);

#pragma unroll
    for (int i = 0; i < 4; i++) {
        int c = i * 256 + tid;
        y[c] = (v[i] - mu) * inv * w[c] + bb[c];
    }
}

// ---------------------------------------------------------------------------
// Launch
// ---------------------------------------------------------------------------
extern "C" void kernel_launch(void* const* d_in, const int* in_sizes, int n_in,
                              void* d_out, int out_size)
{
    const float* x     = (const float*)d_in[0];
    const float* qvk_w = (const float*)d_in[1];
    const float* qvk_b = (const float*)d_in[2];
    const float* qh_w  = (const float*)d_in[3];
    const float* qh_b  = (const float*)d_in[4];
    const float* kh_w  = (const float*)d_in[5];
    const float* kh_b  = (const float*)d_in[6];
    const float* vh_w  = (const float*)d_in[7];
    const float* vh_b  = (const float*)d_in[8];
    const float* o_w   = (const float*)d_in[9];
    const float* o_b   = (const float*)d_in[10];
    const float* ln1_w = (const float*)d_in[11];
    const float* ln1_b = (const float*)d_in[12];
    const float* m1_w  = (const float*)d_in[13];
    const float* m1_b  = (const float*)d_in[14];
    const float* m2_w  = (const float*)d_in[15];
    const float* m2_b  = (const float*)d_in[16];
    const float* ln2_w = (const float*)d_in[17];
    const float* ln2_b = (const float*)d_in[18];
    float* out = (float*)d_out;

    float *qvk, *Qb, *Kb, *Vb, *att, *t1, *t2, *h1, *t3;
    cudaGetSymbolAddress((void**)&qvk, g_qvk);
    cudaGetSymbolAddress((void**)&Qb,  g_Q);
    cudaGetSymbolAddress((void**)&Kb,  g_K);
    cudaGetSymbolAddress((void**)&Vb,  g_V);
    cudaGetSymbolAddress((void**)&att, g_att);
    cudaGetSymbolAddress((void**)&t1,  g_t1);
    cudaGetSymbolAddress((void**)&t2,  g_t2);
    cudaGetSymbolAddress((void**)&h1,  g_h1);
    cudaGetSymbolAddress((void**)&t3,  g_t3);

    // Opt in to >48KB dynamic smem for flash_attn (host attr call, not captured)
    cudaFuncSetAttribute(flash_attn,
                         cudaFuncAttributeMaxDynamicSharedMemorySize,
                         FA_SMEM_BYTES);

    const dim3 thr(256);
    const float invscale = 1.0f / (sqrtf((float)DPH) + 1e-10f);

    // 1. qvk = relu6(x @ qvk_w + qvk_b)               [4096, 3072]
    gemm_relu6<<<dim3(DH3 / 128, TTOK / 128), thr>>>(
        x, DIM, qvk_w, DH3, qvk_b, qvk, DH3, DIM, 0);

    // 2. Q/K/V head projections -> [b=n*16+h][m][dph]
    gemm_relu6<<<dim3(DIM / 128, TTOK / 128), thr>>>(
        qvk,            DH3, qh_w, DIM, qh_b, Qb, 0, DIM, 1);
    gemm_relu6<<<dim3(DIM / 128, TTOK / 128), thr>>>(
        qvk + DIM,      DH3, kh_w, DIM, kh_b, Kb, 0, DIM, 1);
    gemm_relu6<<<dim3(DIM / 128, TTOK / 128), thr>>>(
        qvk + 2 * DIM,  DH3, vh_w, DIM, vh_b, Vb, 0, DIM, 1);

    // 3-5. Fused scores+softmax+PV
    flash_attn<<<dim3(1, MSEQ / 64, NB * NH), thr, FA_SMEM_BYTES>>>(
        Qb, Kb, Vb, att, invscale);

    // 6. t1 = relu6(att @ o_w + o_b)
    gemm_relu6<<<dim3(DIM / 128, TTOK / 128), thr>>>(
        att, DIM, o_w, DIM, o_b, t1, DIM, DIM, 0);

    // 7. t2 = LN1(t1)
    layernorm_rows<<<TTOK, thr>>>(t1, ln1_w, ln1_b, t2);

    // 8. h1 = relu6(t2 @ m1_w + m1_b)                 [4096, 2048]
    gemm_relu6<<<dim3(DEXP / 128, TTOK / 128), thr>>>(
        t2, DIM, m1_w, DEXP, m1_b, h1, DEXP, DIM, 0);

    // 9. t3 = relu6(h1 @ m2_w + m2_b)                 [4096, 1024]
    gemm_relu6<<<dim3(DIM / 128, TTOK / 128), thr>>>(
        h1, DEXP, m2_w, DIM, m2_b, t3, DIM, DEXP, 0);

    // 10. out = LN2(t3)
    layernorm_rows<<<TTOK, thr>>>(t3, ln2_w, ln2_b, out);
}

// round 5
// speedup vs baseline: 1.5338x; 1.5338x over previous
#include <cuda_runtime.h>
#include <cuda_bf16.h>
#include <math.h>
#include <stdint.h>

// Problem constants
#define NB    2
#define MSEQ  2048
#define DIM   1024
#define NH    16
#define DPH   64
#define TTOK  (NB * MSEQ)      // 4096 tokens
#define DH3   (3 * DIM)        // 3072
#define DEXP  (2 * DIM)        // 2048

// ===========================================================================
// PTX helpers (ALL base-target sm_80-class: no tcgen05 / no 'a'-features)
// ===========================================================================
__device__ __forceinline__ uint32_t smem_to_u32(const void* smem_ptr) {
    uint32_t addr;
    asm("{ .reg .u64 tmp; cvta.to.shared.u64 tmp, %1; cvt.u32.u64 %0, tmp; }"
        : "=r"(addr) : "l"(smem_ptr));
    return addr;
}

#define CP_ASYNC16(dst_u32, src_ptr) \
    asm volatile("cp.async.cg.shared.global [%0], [%1], 16;" \
        :: "r"(dst_u32), "l"(src_ptr) : "memory")

#define CP_COMMIT() \
    asm volatile("cp.async.commit_group;" ::: "memory")

#define CP_WAIT1() \
    asm volatile("cp.async.wait_group 1;" ::: "memory")

#define CP_WAIT0() \
    asm volatile("cp.async.wait_group 0;" ::: "memory")

#define LDM_X4(R, addr) \
    asm volatile("ldmatrix.sync.aligned.m8n8.x4.shared.b16 {%0,%1,%2,%3}, [%4];" \
        : "=r"((R)[0]), "=r"((R)[1]), "=r"((R)[2]), "=r"((R)[3]) : "r"(addr))

#define MMA_BF16(D, A, B0, B1) \
    asm volatile("mma.sync.aligned.m16n8k16.row.col.f32.bf16.bf16.f32 " \
        "{%0,%1,%2,%3}, {%4,%5,%6,%7}, {%8,%9}, {%0,%1,%2,%3};" \
        : "+f"((D)[0]), "+f"((D)[1]), "+f"((D)[2]), "+f"((D)[3]) \
        : "r"((A)[0]), "r"((A)[1]), "r"((A)[2]), "r"((A)[3]), "r"(B0), "r"(B1))

// ===========================================================================
// Scratch (allocation-free: __device__ globals)
// ===========================================================================
__device__ float g_Q[NB * NH * MSEQ * DPH];
__device__ float g_K[NB * NH * MSEQ * DPH];
__device__ float g_V[NB * NH * MSEQ * DPH];
__device__ float g_t1[TTOK * DIM];
__device__ float g_t3[TTOK * DIM];
// bf16 hi/lo activation pairs
__device__ __nv_bfloat16 g_xhi[TTOK * DIM],  g_xlo[TTOK * DIM];
__device__ __nv_bfloat16 g_qvkhi[TTOK * DH3], g_qvklo[TTOK * DH3];
__device__ __nv_bfloat16 g_atthi[TTOK * DIM], g_attlo[TTOK * DIM];
__device__ __nv_bfloat16 g_ln1hi[TTOK * DIM], g_ln1lo[TTOK * DIM];
__device__ __nv_bfloat16 g_m1hi[TTOK * DEXP], g_m1lo[TTOK * DEXP];
// transposed bf16 hi/lo weights: [N][K] K-major
__device__ __nv_bfloat16 g_wqvkhi[DH3 * DIM], g_wqvklo[DH3 * DIM];
__device__ __nv_bfloat16 g_wqhi[DIM * DIM],   g_wqlo[DIM * DIM];
__device__ __nv_bfloat16 g_wkhi[DIM * DIM],   g_wklo[DIM * DIM];
__device__ __nv_bfloat16 g_wvhi[DIM * DIM],   g_wvlo[DIM * DIM];
__device__ __nv_bfloat16 g_wohi[DIM * DIM],   g_wolo[DIM * DIM];
__device__ __nv_bfloat16 g_wm1hi[DEXP * DIM], g_wm1lo[DEXP * DIM];
__device__ __nv_bfloat16 g_wm2hi[DIM * DEXP], g_wm2lo[DIM * DEXP];

__device__ __forceinline__ float relu6f(float v) {
    return fminf(fmaxf(v, 0.0f), 6.0f);
}

// ===========================================================================
// Weight transpose + split:  W[K,N] fp32 -> Thi/Tlo[N,K] bf16
// ===========================================================================
__global__ void __launch_bounds__(256) transpose_split(
    const float* __restrict__ W, int Kdim, int Ndim,
    __nv_bfloat16* __restrict__ Thi, __nv_bfloat16* __restrict__ Tlo)
{
    __shared__ float t[32][33];
    const int k0 = blockIdx.y * 32, n0 = blockIdx.x * 32;
    const int tx = threadIdx.x & 31, ty = threadIdx.x >> 5;  // ty 0..7
#pragma unroll
    for (int j = 0; j < 4; j++)
        t[ty + 8 * j][tx] = W[(size_t)(k0 + ty + 8 * j) * Ndim + n0 + tx];
    __syncthreads();
#pragma unroll
    for (int j = 0; j < 4; j++) {
        float v = t[tx][ty + 8 * j];   // = W[k0+tx][n0+ty+8j]
        __nv_bfloat16 hi = __float2bfloat16(v);
        size_t o = (size_t)(n0 + ty + 8 * j) * Kdim + k0 + tx;
        Thi[o] = hi;
        Tlo[o] = __float2bfloat16(v - __bfloat162float(hi));
    }
}

// Elementwise split: X fp32 -> hi/lo bf16. n must be multiple of 1024.
__global__ void __launch_bounds__(256) split_pair(
    const float* __restrict__ X,
    __nv_bfloat16* __restrict__ Hi, __nv_bfloat16* __restrict__ Lo)
{
    int i4 = blockIdx.x * 256 + threadIdx.x;
    float4 v = ((const float4*)X)[i4];
    float vv[4] = {v.x, v.y, v.z, v.w};
#pragma unroll
    for (int j = 0; j < 4; j++) {
        __nv_bfloat16 hi = __float2bfloat16(vv[j]);
        Hi[i4 * 4 + j] = hi;
        Lo[i4 * 4 + j] = __float2bfloat16(vv[j] - __bfloat162float(hi));
    }
}

// ===========================================================================
// mma.sync split-bf16 GEMM: C = relu6(A[M,K] @ B^T[N,K] + bias)
// 128x128 block, BK=32, 256 threads (8 warps, 4x2 of 32x64 warp tiles),
// 3-stage cp.async pipeline, 80B smem row pitch (conflict-free ldmatrix).
// 3 MMA passes per k-step: Ahi*Bhi + Ahi*Blo + Alo*Bhi  (fp32 accum).
// ===========================================================================
#define BM 128
#define BN 128
#define BK 32
#define NSTAGE 3
#define ROWB 80
#define TILE_SZ  (128 * ROWB)       // 10240 B per tile
#define STAGE_SZ (4 * TILE_SZ)      // Ahi, Alo, Bhi, Blo
#define GEMM_SMEM (NSTAGE * STAGE_SZ)  // 122880 B

#define OUT_F32  0
#define OUT_PAIR 1
#define OUT_HEAD 2

__global__ void __launch_bounds__(256) gemm_mma(
    const __nv_bfloat16* __restrict__ Ahi, const __nv_bfloat16* __restrict__ Alo, int lda,
    const __nv_bfloat16* __restrict__ Bhi, const __nv_bfloat16* __restrict__ Blo,
    const float* __restrict__ bias,
    float* __restrict__ Cf,
    __nv_bfloat16* __restrict__ Chi, __nv_bfloat16* __restrict__ Clo,
    int ldc, int K, int mode)
{
    extern __shared__ char sm_raw[];
    const uint32_t sbase = smem_to_u32(sm_raw);
    const int tid  = threadIdx.x;
    const int lane = tid & 31;
    const int wid  = tid >> 5;
    const int wr   = wid & 3;     // warp row: m offset wr*32
    const int wc   = wid >> 2;    // warp col: n offset wc*64
    const int m0   = blockIdx.y * BM;
    const int n0   = blockIdx.x * BN;

    float acc[2][8][4];
#pragma unroll
    for (int i = 0; i < 2; i++)
#pragma unroll
        for (int j = 0; j < 8; j++)
#pragma unroll
            for (int e = 0; e < 4; e++) acc[i][j][e] = 0.0f;

    // ---- async load of one BK-chunk into stage c%NSTAGE ----
    auto load_chunk = [&](int c) {
        const uint32_t sb = sbase + (c % NSTAGE) * STAGE_SZ;
#pragma unroll
        for (int t = 0; t < 8; t++) {
            const int tile  = t >> 1;                  // compile-time per t
            const int chunk = (t & 1) * 256 + tid;     // 0..511
            const int row   = chunk >> 2;              // 0..127
            const int col   = chunk & 3;               // 16B unit within 64B row
            const __nv_bfloat16* src;
            if (tile == 0)
                src = Ahi + (size_t)(m0 + row) * lda + c * BK + col * 8;
            else if (tile == 1)
                src = Alo + (size_t)(m0 + row) * lda + c * BK + col * 8;
            else if (tile == 2)
                src = Bhi + (size_t)(n0 + row) * K + c * BK + col * 8;
            else
                src = Blo + (size_t)(n0 + row) * K + c * BK + col * 8;
            CP_ASYNC16(sb + tile * TILE_SZ + (uint32_t)(row * ROWB + col * 16), src);
        }
    };

    // ---- compute one BK-chunk from stage c%NSTAGE ----
    auto compute = [&](int c) {
        const uint32_t sb = sbase + (c % NSTAGE) * STAGE_SZ;
        // A ldmatrix lane map: row = lane&15, colByte = (lane>>4)*16
        const uint32_t aB = sb + (uint32_t)((wr * 32 + (lane & 15)) * ROWB + (lane >> 4) * 16);
        // B ldmatrix x4 lane map: row = (lane&7) + ((lane>>4)&1)*8, colByte = ((lane>>3)&1)*16
        const uint32_t bB = sb + 2 * TILE_SZ
            + (uint32_t)((wc * 64 + (lane & 7) + ((lane >> 4) & 1) * 8) * ROWB
                         + ((lane >> 3) & 1) * 16);
#pragma unroll
        for (int s = 0; s < 2; s++) {          // two k16 steps per BK=32
            uint32_t ah[2][4], al[2][4];
#pragma unroll
            for (int i = 0; i < 2; i++) {
                LDM_X4(ah[i], aB + (uint32_t)(i * 16 * ROWB + s * 32));
                LDM_X4(al[i], aB + TILE_SZ + (uint32_t)(i * 16 * ROWB + s * 32));
            }
#pragma unroll
            for (int jj = 0; jj < 4; jj++) {   // each jj covers n16 (two n8 frags)
                uint32_t bh[4], bl[4];
                LDM_X4(bh, bB + (uint32_t)(jj * 16 * ROWB + s * 32));
                LDM_X4(bl, bB + TILE_SZ + (uint32_t)(jj * 16 * ROWB + s * 32));
#pragma unroll
                for (int i = 0; i < 2; i++) {
                    MMA_BF16(acc[i][jj * 2],     ah[i], bh[0], bh[1]);
                    MMA_BF16(acc[i][jj * 2 + 1], ah[i], bh[2], bh[3]);
                    MMA_BF16(acc[i][jj * 2],     ah[i], bl[0], bl[1]);
                    MMA_BF16(acc[i][jj * 2 + 1], ah[i], bl[2], bl[3]);
                    MMA_BF16(acc[i][jj * 2],     al[i], bh[0], bh[1]);
                    MMA_BF16(acc[i][jj * 2 + 1], al[i], bh[2], bh[3]);
                }
            }
        }
    };

    const int nchunk = K / BK;
    load_chunk(0); CP_COMMIT();
    load_chunk(1); CP_COMMIT();

    for (int c = 0; c < nchunk; c++) {
        CP_WAIT1();            // chunk c resident
        __syncthreads();       // visible to all; prior compute done
        if (c + 2 < nchunk) load_chunk(c + 2);
        CP_COMMIT();           // commit every iter (possibly empty group)
        compute(c);
    }
    CP_WAIT0();

    // ---- epilogue: bias + relu6, three output modes ----
#pragma unroll
    for (int i = 0; i < 2; i++) {
        const int r0 = m0 + wr * 32 + i * 16 + (lane >> 2);
#pragma unroll
        for (int jf = 0; jf < 8; jf++) {
            const int c0 = n0 + wc * 64 + jf * 8 + (lane & 3) * 2;
#pragma unroll
            for (int e = 0; e < 4; e++) {
                const int m = r0 + (e >> 1) * 8;
                const int n = c0 + (e & 1);
                float v = relu6f(acc[i][jf][e] + bias[n]);
                if (mode == OUT_F32) {
                    Cf[(size_t)m * ldc + n] = v;
                } else if (mode == OUT_PAIR) {
                    __nv_bfloat16 hi = __float2bfloat16(v);
                    size_t o = (size_t)m * ldc + n;
                    Chi[o] = hi;
                    Clo[o] = __float2bfloat16(v - __bfloat162float(hi));
                } else {
                    int nb = m >> 11, mm = m & 2047;
                    int h = n & 15, dph = n >> 4;
                    Cf[((((size_t)(nb * 16 + h) * 2048) + mm) * 64) + dph] = v;
                }
            }
        }
    }
}

// ===========================================================================
// Fused flash attention (fp32, head dim 64), bf16 hi/lo output.
// Grid: (1, MSEQ/64, NB*NH). Block: 256. Dynamic smem 68KB.
// ===========================================================================
#define FA_SMEM_BYTES (4 * 64 * 68 * 4)

__global__ void __launch_bounds__(256) flash_attn(
    const float* __restrict__ Qb, const float* __restrict__ Kb,
    const float* __restrict__ Vb,
    __nv_bfloat16* __restrict__ outhi, __nv_bfloat16* __restrict__ outlo,
    float invscale)
{
    extern __shared__ float smem[];
    float (*Qs)[68] = (float (*)[68])(smem);                 // [d][m]
    float (*Ks)[68] = (float (*)[68])(smem + 64 * 68);       // [d][k]
    float (*Vs)[68] = (float (*)[68])(smem + 2 * 64 * 68);   // [k][dph]
    float (*Ps)[68] = (float (*)[68])(smem + 3 * 64 * 68);   // [k][m]

    const int b = blockIdx.z;
    const int n = b >> 4, h = b & 15;
    const float* Q  = Qb + (size_t)b * MSEQ * DPH;
    const float* Kp = Kb + (size_t)b * MSEQ * DPH;
    const float* Vp = Vb + (size_t)b * MSEQ * DPH;
    const int q0 = blockIdx.y * 64;

    const int tid = threadIdx.x;
    const int ty = tid >> 4, tx = tid & 15;

#pragma unroll
    for (int i = 0; i < 4; i++) {
        int f = i * 256 + tid;
        int r  = f >> 4;
        int c4 = (f & 15) * 4;
        float4 qv = *(const float4*)(Q + (size_t)(q0 + r) * DPH + c4);
        Qs[c4 + 0][r] = qv.x; Qs[c4 + 1][r] = qv.y;
        Qs[c4 + 2][r] = qv.z; Qs[c4 + 3][r] = qv.w;
    }

    float m_run[4], l_run[4];
    float acc[4][4];
#pragma unroll
    for (int i = 0; i < 4; i++) {
        m_run[i] = -3.4e38f;
        l_run[i] = 0.0f;
#pragma unroll
        for (int j = 0; j < 4; j++) acc[i][j] = 0.0f;
    }

    for (int k0 = 0; k0 < MSEQ; k0 += 64) {
        __syncthreads();
#pragma unroll
        for (int i = 0; i < 4; i++) {
            int f = i * 256 + tid;
            int r  = f >> 4;
            int c4 = (f & 15) * 4;
            float4 kv = *(const float4*)(Kp + (size_t)(k0 + r) * DPH + c4);
            float4 vv = *(const float4*)(Vp + (size_t)(k0 + r) * DPH + c4);
            Ks[c4 + 0][r] = kv.x; Ks[c4 + 1][r] = kv.y;
            Ks[c4 + 2][r] = kv.z; Ks[c4 + 3][r] = kv.w;
            *(float4*)&Vs[r][c4] = vv;
        }
        __syncthreads();

        float s[4][4];
#pragma unroll
        for (int i = 0; i < 4; i++)
#pragma unroll
            for (int j = 0; j < 4; j++) s[i][j] = 0.0f;

#pragma unroll 8
        for (int d = 0; d < 64; d++) {
            float4 a4 = *(const float4*)&Qs[d][ty * 4];
            float4 b4 = *(const float4*)&Ks[d][tx * 4];
            float a[4] = {a4.x, a4.y, a4.z, a4.w};
            float bb[4] = {b4.x, b4.y, b4.z, b4.w};
#pragma unroll
            for (int i = 0; i < 4; i++)
#pragma unroll
                for (int j = 0; j < 4; j++)
                    s[i][j] += a[i] * bb[j];
        }

#pragma unroll
        for (int i = 0; i < 4; i++) {
            float mx = fmaxf(fmaxf(s[i][0] * invscale, s[i][1] * invscale),
                             fmaxf(s[i][2] * invscale, s[i][3] * invscale));
#pragma unroll
            for (int off = 8; off >= 1; off >>= 1)
                mx = fmaxf(mx, __shfl_xor_sync(0xffffffffu, mx, off));
            float m_new = fmaxf(m_run[i], mx);
            float corr = __expf(m_run[i] - m_new);

            float p0 = __expf(s[i][0] * invscale - m_new);
            float p1 = __expf(s[i][1] * invscale - m_new);
            float p2 = __expf(s[i][2] * invscale - m_new);
            float p3 = __expf(s[i][3] * invscale - m_new);
            s[i][0] = p0; s[i][1] = p1; s[i][2] = p2; s[i][3] = p3;

            float rs = p0 + p1 + p2 + p3;
#pragma unroll
            for (int off = 8; off >= 1; off >>= 1)
                rs += __shfl_xor_sync(0xffffffffu, rs, off);

            l_run[i] = l_run[i] * corr + rs;
            m_run[i] = m_new;
#pragma unroll
            for (int j = 0; j < 4; j++) acc[i][j] *= corr;
        }

#pragma unroll
        for (int i = 0; i < 4; i++)
#pragma unroll
            for (int j = 0; j < 4; j++)
                Ps[tx * 4 + j][ty * 4 + i] = s[i][j];
        __syncthreads();

#pragma unroll 8
        for (int kk = 0; kk < 64; kk++) {
            float4 a4 = *(const float4*)&Ps[kk][ty * 4];
            float4 b4 = *(const float4*)&Vs[kk][tx * 4];
            float a[4] = {a4.x, a4.y, a4.z, a4.w};
            float bb[4] = {b4.x, b4.y, b4.z, b4.w};
#pragma unroll
            for (int i = 0; i < 4; i++)
#pragma unroll
                for (int j = 0; j < 4; j++)
                    acc[i][j] += a[i] * bb[j];
        }
    }

#pragma unroll
    for (int i = 0; i < 4; i++) {
        float inv = 1.0f / l_run[i];
        int tok = n * MSEQ + q0 + ty * 4 + i;
#pragma unroll
        for (int j = 0; j < 4; j++) {
            int c = h * 64 + tx * 4 + j;
            float v = acc[i][j] * inv;
            __nv_bfloat16 hi = __float2bfloat16(v);
            size_t o = (size_t)tok * DIM + c;
            outhi[o] = hi;
            outlo[o] = __float2bfloat16(v - __bfloat162float(hi));
        }
    }
}

// ===========================================================================
// LayerNorm over last dim (1024). PAIR=1: bf16 hi/lo out; PAIR=0: fp32 out.
// ===========================================================================
template <int PAIR>
__global__ void __launch_bounds__(256) layernorm_rows(
    const float* __restrict__ X, const float* __restrict__ w,
    const float* __restrict__ bb, float* __restrict__ Yf,
    __nv_bfloat16* __restrict__ Yhi, __nv_bfloat16* __restrict__ Ylo)
{
    const int row = blockIdx.x;
    const float* x = X + (size_t)row * DIM;
    const int tid = threadIdx.x;

    float v[4];
    float s = 0.0f;
#pragma unroll
    for (int i = 0; i < 4; i++) {
        v[i] = x[i * 256 + tid];
        s += v[i];
    }

    __shared__ float red[256];
    red[tid] = s;
    __syncthreads();
#pragma unroll
    for (int st = 128; st >= 1; st >>= 1) {
        if (tid < st) red[tid] += red[tid + st];
        __syncthreads();
    }
    float mu = red[0] * (1.0f / DIM);
    __syncthreads();

    float vs = 0.0f;
#pragma unroll
    for (int i = 0; i < 4; i++) {
        float d = v[i] - mu;
        vs += d * d;
    }
    red[tid] = vs;
    __syncthreads();
#pragma unroll
    for (int st = 128; st >= 1; st >>= 1) {
        if (tid < st) red[tid] += red[tid + st];
        __syncthreads();
    }
    float var = red[0] * (1.0f / DIM);
    float inv = rsqrtf(var + 1e-5f);

#pragma unroll
    for (int i = 0; i < 4; i++) {
        int c = i * 256 + tid;
        float y = (v[i] - mu) * inv * w[c] + bb[c];
        if (PAIR) {
            __nv_bfloat16 hi = __float2bfloat16(y);
            size_t o = (size_t)row * DIM + c;
            Yhi[o] = hi;
            Ylo[o] = __float2bfloat16(y - __bfloat162float(hi));
        } else {
            Yf[(size_t)row * DIM + c] = y;
        }
    }
}

// ===========================================================================
// Launch
// ===========================================================================
extern "C" void kernel_launch(void* const* d_in, const int* in_sizes, int n_in,
                              void* d_out, int out_size)
{
    const float* x     = (const float*)d_in[0];
    const float* qvk_w = (const float*)d_in[1];
    const float* qvk_b = (const float*)d_in[2];
    const float* qh_w  = (const float*)d_in[3];
    const float* qh_b  = (const float*)d_in[4];
    const float* kh_w  = (const float*)d_in[5];
    const float* kh_b  = (const float*)d_in[6];
    const float* vh_w  = (const float*)d_in[7];
    const float* vh_b  = (const float*)d_in[8];
    const float* o_w   = (const float*)d_in[9];
    const float* o_b   = (const float*)d_in[10];
    const float* ln1_w = (const float*)d_in[11];
    const float* ln1_b = (const float*)d_in[12];
    const float* m1_w  = (const float*)d_in[13];
    const float* m1_b  = (const float*)d_in[14];
    const float* m2_w  = (const float*)d_in[15];
    const float* m2_b  = (const float*)d_in[16];
    const float* ln2_w = (const float*)d_in[17];
    const float* ln2_b = (const float*)d_in[18];
    float* out = (float*)d_out;

    float *Qb, *Kb, *Vb, *t1, *t3;
    __nv_bfloat16 *xhi, *xlo, *qvkhi, *qvklo, *atthi, *attlo,
                  *ln1hi, *ln1lo, *m1hi, *m1lo;
    __nv_bfloat16 *wqvkhi, *wqvklo, *wqhi, *wqlo, *wkhi, *wklo,
                  *wvhi, *wvlo, *wohi, *wolo, *wm1hi, *wm1lo, *wm2hi, *wm2lo;

    cudaGetSymbolAddress((void**)&Qb,  g_Q);
    cudaGetSymbolAddress((void**)&Kb,  g_K);
    cudaGetSymbolAddress((void**)&Vb,  g_V);
    cudaGetSymbolAddress((void**)&t1,  g_t1);
    cudaGetSymbolAddress((void**)&t3,  g_t3);
    cudaGetSymbolAddress((void**)&xhi, g_xhi);     cudaGetSymbolAddress((void**)&xlo, g_xlo);
    cudaGetSymbolAddress((void**)&qvkhi, g_qvkhi); cudaGetSymbolAddress((void**)&qvklo, g_qvklo);
    cudaGetSymbolAddress((void**)&atthi, g_atthi); cudaGetSymbolAddress((void**)&attlo, g_attlo);
    cudaGetSymbolAddress((void**)&ln1hi, g_ln1hi); cudaGetSymbolAddress((void**)&ln1lo, g_ln1lo);
    cudaGetSymbolAddress((void**)&m1hi, g_m1hi);   cudaGetSymbolAddress((void**)&m1lo, g_m1lo);
    cudaGetSymbolAddress((void**)&wqvkhi, g_wqvkhi); cudaGetSymbolAddress((void**)&wqvklo, g_wqvklo);
    cudaGetSymbolAddress((void**)&wqhi, g_wqhi);   cudaGetSymbolAddress((void**)&wqlo, g_wqlo);
    cudaGetSymbolAddress((void**)&wkhi, g_wkhi);   cudaGetSymbolAddress((void**)&wklo, g_wklo);
    cudaGetSymbolAddress((void**)&wvhi, g_wvhi);   cudaGetSymbolAddress((void**)&wvlo, g_wvlo);
    cudaGetSymbolAddress((void**)&wohi, g_wohi);   cudaGetSymbolAddress((void**)&wolo, g_wolo);
    cudaGetSymbolAddress((void**)&wm1hi, g_wm1hi); cudaGetSymbolAddress((void**)&wm1lo, g_wm1lo);
    cudaGetSymbolAddress((void**)&wm2hi, g_wm2hi); cudaGetSymbolAddress((void**)&wm2lo, g_wm2lo);

    cudaFuncSetAttribute(flash_attn,
                         cudaFuncAttributeMaxDynamicSharedMemorySize, FA_SMEM_BYTES);
    cudaFuncSetAttribute(gemm_mma,
                         cudaFuncAttributeMaxDynamicSharedMemorySize, GEMM_SMEM);

    const dim3 thr(256);
    const float invscale = 1.0f / (sqrtf((float)DPH) + 1e-10f);

    // --- weight transpose + split ---
    transpose_split<<<dim3(DH3 / 32, DIM / 32), thr>>>(qvk_w, DIM, DH3, wqvkhi, wqvklo);
    transpose_split<<<dim3(DIM / 32, DIM / 32), thr>>>(qh_w, DIM, DIM, wqhi, wqlo);
    transpose_split<<<dim3(DIM / 32, DIM / 32), thr>>>(kh_w, DIM, DIM, wkhi, wklo);
    transpose_split<<<dim3(DIM / 32, DIM / 32), thr>>>(vh_w, DIM, DIM, wvhi, wvlo);
    transpose_split<<<dim3(DIM / 32, DIM / 32), thr>>>(o_w,  DIM, DIM, wohi, wolo);
    transpose_split<<<dim3(DEXP / 32, DIM / 32), thr>>>(m1_w, DIM, DEXP, wm1hi, wm1lo);
    transpose_split<<<dim3(DIM / 32, DEXP / 32), thr>>>(m2_w, DEXP, DIM, wm2hi, wm2lo);

    // --- input split ---
    split_pair<<<TTOK * DIM / 1024, thr>>>(x, xhi, xlo);

    // 1. qvk = relu6(x @ qvk_w + b)  -> bf16 pair
    gemm_mma<<<dim3(DH3 / BN, TTOK / BM), thr, GEMM_SMEM>>>(
        xhi, xlo, DIM, wqvkhi, wqvklo, qvk_b,
        nullptr, qvkhi, qvklo, DH3, DIM, OUT_PAIR);

    // 2. Q/K/V head projections -> fp32 [b][m][dph]
    gemm_mma<<<dim3(DIM / BN, TTOK / BM), thr, GEMM_SMEM>>>(
        qvkhi,            qvklo,            DH3, wqhi, wqlo, qh_b,
        Qb, nullptr, nullptr, 0, DIM, OUT_HEAD);
    gemm_mma<<<dim3(DIM / BN, TTOK / BM), thr, GEMM_SMEM>>>(
        qvkhi + DIM,      qvklo + DIM,      DH3, wkhi, wklo, kh_b,
        Kb, nullptr, nullptr, 0, DIM, OUT_HEAD);
    gemm_mma<<<dim3(DIM / BN, TTOK / BM), thr, GEMM_SMEM>>>(
        qvkhi + 2 * DIM,  qvklo + 2 * DIM,  DH3, wvhi, wvlo, vh_b,
        Vb, nullptr, nullptr, 0, DIM, OUT_HEAD);

    // 3-5. Fused attention -> bf16 pair
    flash_attn<<<dim3(1, MSEQ / 64, NB * NH), thr, FA_SMEM_BYTES>>>(
        Qb, Kb, Vb, atthi, attlo, invscale);

    // 6. t1 = relu6(att @ o_w + o_b)  fp32
    gemm_mma<<<dim3(DIM / BN, TTOK / BM), thr, GEMM_SMEM>>>(
        atthi, attlo, DIM, wohi, wolo, o_b,
        t1, nullptr, nullptr, DIM, DIM, OUT_F32);

    // 7. LN1 -> bf16 pair
    layernorm_rows<1><<<TTOK, thr>>>(t1, ln1_w, ln1_b, nullptr, ln1hi, ln1lo);

    // 8. m1 -> bf16 pair
    gemm_mma<<<dim3(DEXP / BN, TTOK / BM), thr, GEMM_SMEM>>>(
        ln1hi, ln1lo, DIM, wm1hi, wm1lo, m1_b,
        nullptr, m1hi, m1lo, DEXP, DIM, OUT_PAIR);

    // 9. m2 -> fp32
    gemm_mma<<<dim3(DIM / BN, TTOK / BM), thr, GEMM_SMEM>>>(
        m1hi, m1lo, DEXP, wm2hi, wm2lo, m2_b,
        t3, nullptr, nullptr, DIM, DEXP, OUT_F32);

    // 10. LN2 -> out fp32
    layernorm_rows<0><<<TTOK, thr>>>(t3, ln2_w, ln2_b, out, nullptr, nullptr);
}

// round 7
// speedup vs baseline: 2.1866x; 1.4257x over previous
#include <cuda_runtime.h>
#include <cuda_bf16.h>
#include <math.h>
#include <stdint.h>

// Problem constants
#define NB    2
#define MSEQ  2048
#define DIM   1024
#define NH    16
#define DPH   64
#define TTOK  (NB * MSEQ)      // 4096 tokens
#define DH3   (3 * DIM)        // 3072
#define DEXP  (2 * DIM)        // 2048

// ===========================================================================
// PTX helpers (base-target sm_80-class only)
// ===========================================================================
__device__ __forceinline__ uint32_t smem_to_u32(const void* smem_ptr) {
    uint32_t addr;
    asm("{ .reg .u64 tmp; cvta.to.shared.u64 tmp, %1; cvt.u32.u64 %0, tmp; }"
        : "=r"(addr) : "l"(smem_ptr));
    return addr;
}

#define CP_ASYNC16(dst_u32, src_ptr) \
    asm volatile("cp.async.cg.shared.global [%0], [%1], 16;" \
        :: "r"(dst_u32), "l"(src_ptr) : "memory")

#define CP_COMMIT() asm volatile("cp.async.commit_group;" ::: "memory")
#define CP_WAIT1()  asm volatile("cp.async.wait_group 1;" ::: "memory")
#define CP_WAIT0()  asm volatile("cp.async.wait_group 0;" ::: "memory")

#define LDM_X4(R, addr) \
    asm volatile("ldmatrix.sync.aligned.m8n8.x4.shared.b16 {%0,%1,%2,%3}, [%4];" \
        : "=r"((R)[0]), "=r"((R)[1]), "=r"((R)[2]), "=r"((R)[3]) : "r"(addr))

#define LDM_X2(R, addr) \
    asm volatile("ldmatrix.sync.aligned.m8n8.x2.shared.b16 {%0,%1}, [%2];" \
        : "=r"((R)[0]), "=r"((R)[1]) : "r"(addr))

#define MMA_BF16(D, A, B0, B1) \
    asm volatile("mma.sync.aligned.m16n8k16.row.col.f32.bf16.bf16.f32 " \
        "{%0,%1,%2,%3}, {%4,%5,%6,%7}, {%8,%9}, {%0,%1,%2,%3};" \
        : "+f"((D)[0]), "+f"((D)[1]), "+f"((D)[2]), "+f"((D)[3]) \
        : "r"((A)[0]), "r"((A)[1]), "r"((A)[2]), "r"((A)[3]), "r"(B0), "r"(B1))

// pack two fp32 -> bf16x2 (lo in bits 0-15, hi in bits 16-31)
#define PACK_BF16X2(r, vlo, vhi) \
    asm("cvt.rn.bf16x2.f32 %0, %1, %2;" : "=r"(r) : "f"(vhi), "f"(vlo))

// ===========================================================================
// Scratch (allocation-free: __device__ globals)
// ===========================================================================
__device__ float g_t1[TTOK * DIM];
__device__ float g_t3[TTOK * DIM];
// bf16 hi/lo activation pairs
__device__ __nv_bfloat16 g_xhi[TTOK * DIM],  g_xlo[TTOK * DIM];
__device__ __nv_bfloat16 g_qvkhi[TTOK * DH3], g_qvklo[TTOK * DH3];
__device__ __nv_bfloat16 g_atthi[TTOK * DIM], g_attlo[TTOK * DIM];
__device__ __nv_bfloat16 g_ln1hi[TTOK * DIM], g_ln1lo[TTOK * DIM];
__device__ __nv_bfloat16 g_m1hi[TTOK * DEXP], g_m1lo[TTOK * DEXP];
// attention operands, bf16 hi/lo
__device__ __nv_bfloat16 g_Qhi[NB * NH * MSEQ * DPH], g_Qlo[NB * NH * MSEQ * DPH];   // [b][m][64]
__device__ __nv_bfloat16 g_Khi[NB * NH * MSEQ * DPH], g_Klo[NB * NH * MSEQ * DPH];   // [b][m][64]
__device__ __nv_bfloat16 g_Vthi[NB * NH * DPH * MSEQ], g_Vtlo[NB * NH * DPH * MSEQ]; // [b][dph][m]
// transposed bf16 hi/lo weights: [N][K] K-major
__device__ __nv_bfloat16 g_wqvkhi[DH3 * DIM], g_wqvklo[DH3 * DIM];
__device__ __nv_bfloat16 g_wqhi[DIM * DIM],   g_wqlo[DIM * DIM];
__device__ __nv_bfloat16 g_wkhi[DIM * DIM],   g_wklo[DIM * DIM];
__device__ __nv_bfloat16 g_wvhi[DIM * DIM],   g_wvlo[DIM * DIM];
__device__ __nv_bfloat16 g_wohi[DIM * DIM],   g_wolo[DIM * DIM];
__device__ __nv_bfloat16 g_wm1hi[DEXP * DIM], g_wm1lo[DEXP * DIM];
__device__ __nv_bfloat16 g_wm2hi[DIM * DEXP], g_wm2lo[DIM * DEXP];

__device__ __forceinline__ float relu6f(float v) {
    return fminf(fmaxf(v, 0.0f), 6.0f);
}

// ===========================================================================
// Weight transpose + split:  W[K,N] fp32 -> Thi/Tlo[N,K] bf16
// ===========================================================================
__global__ void __launch_bounds__(256) transpose_split(
    const float* __restrict__ W, int Kdim, int Ndim,
    __nv_bfloat16* __restrict__ Thi, __nv_bfloat16* __restrict__ Tlo)
{
    __shared__ float t[32][33];
    const int k0 = blockIdx.y * 32, n0 = blockIdx.x * 32;
    const int tx = threadIdx.x & 31, ty = threadIdx.x >> 5;
#pragma unroll
    for (int j = 0; j < 4; j++)
        t[ty + 8 * j][tx] = W[(size_t)(k0 + ty + 8 * j) * Ndim + n0 + tx];
    __syncthreads();
#pragma unroll
    for (int j = 0; j < 4; j++) {
        float v = t[tx][ty + 8 * j];
        __nv_bfloat16 hi = __float2bfloat16(v);
        size_t o = (size_t)(n0 + ty + 8 * j) * Kdim + k0 + tx;
        Thi[o] = hi;
        Tlo[o] = __float2bfloat16(v - __bfloat162float(hi));
    }
}

__global__ void __launch_bounds__(256) split_pair(
    const float* __restrict__ X,
    __nv_bfloat16* __restrict__ Hi, __nv_bfloat16* __restrict__ Lo)
{
    int i4 = blockIdx.x * 256 + threadIdx.x;
    float4 v = ((const float4*)X)[i4];
    float vv[4] = {v.x, v.y, v.z, v.w};
#pragma unroll
    for (int j = 0; j < 4; j++) {
        __nv_bfloat16 hi = __float2bfloat16(vv[j]);
        Hi[i4 * 4 + j] = hi;
        Lo[i4 * 4 + j] = __float2bfloat16(vv[j] - __bfloat162float(hi));
    }
}

// ===========================================================================
// mma.sync split-bf16 GEMM: C = relu6(A[M,K] @ B^T[N,K] + bias)
// (validated in R5) with new output modes for attention operand layouts.
// ===========================================================================
#define BM 128
#define BN 128
#define BK 32
#define NSTAGE 3
#define ROWB 80
#define TILE_SZ  (128 * ROWB)
#define STAGE_SZ (4 * TILE_SZ)
#define GEMM_SMEM (NSTAGE * STAGE_SZ)

#define OUT_F32    0
#define OUT_PAIR   1
#define OUT_QKPAIR 2   // bf16 hi/lo head-scatter  [b][m][64]
#define OUT_VT     3   // bf16 hi/lo transposed    [b][dph][m]

__global__ void __launch_bounds__(256) gemm_mma(
    const __nv_bfloat16* __restrict__ Ahi, const __nv_bfloat16* __restrict__ Alo, int lda,
    const __nv_bfloat16* __restrict__ Bhi, const __nv_bfloat16* __restrict__ Blo,
    const float* __restrict__ bias,
    float* __restrict__ Cf,
    __nv_bfloat16* __restrict__ Chi, __nv_bfloat16* __restrict__ Clo,
    int ldc, int K, int mode)
{
    extern __shared__ char sm_raw[];
    const uint32_t sbase = smem_to_u32(sm_raw);
    const int tid  = threadIdx.x;
    const int lane = tid & 31;
    const int wid  = tid >> 5;
    const int wr   = wid & 3;
    const int wc   = wid >> 2;
    const int m0   = blockIdx.y * BM;
    const int n0   = blockIdx.x * BN;

    float acc[2][8][4];
#pragma unroll
    for (int i = 0; i < 2; i++)
#pragma unroll
        for (int j = 0; j < 8; j++)
#pragma unroll
            for (int e = 0; e < 4; e++) acc[i][j][e] = 0.0f;

    auto load_chunk = [&](int c) {
        const uint32_t sb = sbase + (c % NSTAGE) * STAGE_SZ;
#pragma unroll
        for (int t = 0; t < 8; t++) {
            const int tile  = t >> 1;
            const int chunk = (t & 1) * 256 + tid;
            const int row   = chunk >> 2;
            const int col   = chunk & 3;
            const __nv_bfloat16* src;
            if (tile == 0)
                src = Ahi + (size_t)(m0 + row) * lda + c * BK + col * 8;
            else if (tile == 1)
                src = Alo + (size_t)(m0 + row) * lda + c * BK + col * 8;
            else if (tile == 2)
                src = Bhi + (size_t)(n0 + row) * K + c * BK + col * 8;
            else
                src = Blo + (size_t)(n0 + row) * K + c * BK + col * 8;
            CP_ASYNC16(sb + tile * TILE_SZ + (uint32_t)(row * ROWB + col * 16), src);
        }
    };

    auto compute = [&](int c) {
        const uint32_t sb = sbase + (c % NSTAGE) * STAGE_SZ;
        const uint32_t aB = sb + (uint32_t)((wr * 32 + (lane & 15)) * ROWB + (lane >> 4) * 16);
        const uint32_t bB = sb + 2 * TILE_SZ
            + (uint32_t)((wc * 64 + (lane & 7) + ((lane >> 4) & 1) * 8) * ROWB
                         + ((lane >> 3) & 1) * 16);
#pragma unroll
        for (int s = 0; s < 2; s++) {
            uint32_t ah[2][4], al[2][4];
#pragma unroll
            for (int i = 0; i < 2; i++) {
                LDM_X4(ah[i], aB + (uint32_t)(i * 16 * ROWB + s * 32));
                LDM_X4(al[i], aB + TILE_SZ + (uint32_t)(i * 16 * ROWB + s * 32));
            }
#pragma unroll
            for (int jj = 0; jj < 4; jj++) {
                uint32_t bh[4], bl[4];
                LDM_X4(bh, bB + (uint32_t)(jj * 16 * ROWB + s * 32));
                LDM_X4(bl, bB + TILE_SZ + (uint32_t)(jj * 16 * ROWB + s * 32));
#pragma unroll
                for (int i = 0; i < 2; i++) {
                    MMA_BF16(acc[i][jj * 2],     ah[i], bh[0], bh[1]);
                    MMA_BF16(acc[i][jj * 2 + 1], ah[i], bh[2], bh[3]);
                    MMA_BF16(acc[i][jj * 2],     ah[i], bl[0], bl[1]);
                    MMA_BF16(acc[i][jj * 2 + 1], ah[i], bl[2], bl[3]);
                    MMA_BF16(acc[i][jj * 2],     al[i], bh[0], bh[1]);
                    MMA_BF16(acc[i][jj * 2 + 1], al[i], bh[2], bh[3]);
                }
            }
        }
    };

    const int nchunk = K / BK;
    load_chunk(0); CP_COMMIT();
    load_chunk(1); CP_COMMIT();

    for (int c = 0; c < nchunk; c++) {
        CP_WAIT1();
        __syncthreads();
        if (c + 2 < nchunk) load_chunk(c + 2);
        CP_COMMIT();
        compute(c);
    }
    CP_WAIT0();

#pragma unroll
    for (int i = 0; i < 2; i++) {
        const int r0 = m0 + wr * 32 + i * 16 + (lane >> 2);
#pragma unroll
        for (int jf = 0; jf < 8; jf++) {
            const int c0 = n0 + wc * 64 + jf * 8 + (lane & 3) * 2;
#pragma unroll
            for (int e = 0; e < 4; e++) {
                const int m = r0 + (e >> 1) * 8;
                const int n = c0 + (e & 1);
                float v = relu6f(acc[i][jf][e] + bias[n]);
                if (mode == OUT_F32) {
                    Cf[(size_t)m * ldc + n] = v;
                } else if (mode == OUT_PAIR) {
                    __nv_bfloat16 hi = __float2bfloat16(v);
                    size_t o = (size_t)m * ldc + n;
                    Chi[o] = hi;
                    Clo[o] = __float2bfloat16(v - __bfloat162float(hi));
                } else {
                    int nb = m >> 11, mm = m & 2047;
                    int h = n & 15, dph = n >> 4;
                    size_t o;
                    if (mode == OUT_QKPAIR)
                        o = ((((size_t)(nb * 16 + h) * 2048) + mm) * 64) + dph;
                    else  // OUT_VT
                        o = (((size_t)(nb * 16 + h) * 64) + dph) * 2048 + mm;
                    __nv_bfloat16 hi = __float2bfloat16(v);
                    Chi[o] = hi;
                    Clo[o] = __float2bfloat16(v - __bfloat162float(hi));
                }
            }
        }
    }
}

// ===========================================================================
// Flash attention on mma.sync (split-bf16).
// Grid: (MSEQ/128, NB*NH). Block: 256 (8 warps x 16 q-rows).
// Q,K: [b][m][64] bf16 hi/lo.  Vt: [b][dph][m] bf16 hi/lo.
// Per k-tile (64): S = 3-pass QK^T mma -> online softmax (fp32 exp) ->
// P packed bf16 A-frags -> PV 2-pass mma with ones-row for row-sum l.
// ===========================================================================
#define AP 144                       // smem pitch (128B data + 16 pad)
#define A_KHI  0
#define A_KLO  (64 * AP)             // 9216
#define A_VHI  (2 * 64 * AP)         // 18432 (72 rows: 64 data + ones + zeros)
#define A_VLO  (A_VHI + 72 * AP)     // 28800
#define A_STAGE (A_VLO + 72 * AP)    // 39168
#define ATTN_SMEM (2 * A_STAGE)      // 78336

__global__ void __launch_bounds__(256) attn_mma(
    const __nv_bfloat16* __restrict__ Qhi, const __nv_bfloat16* __restrict__ Qlo,
    const __nv_bfloat16* __restrict__ Khi, const __nv_bfloat16* __restrict__ Klo,
    const __nv_bfloat16* __restrict__ Vthi, const __nv_bfloat16* __restrict__ Vtlo,
    __nv_bfloat16* __restrict__ atthi, __nv_bfloat16* __restrict__ attlo,
    float inv8)
{
    extern __shared__ char sm_raw[];
    const uint32_t sbase = smem_to_u32(sm_raw);
    const int tid = threadIdx.x;
    const int lane = tid & 31;
    const int wq = tid >> 5;            // warp 0..7, q rows wq*16..+15
    const int b = blockIdx.y;
    const int nb = b >> 4, h = b & 15;
    const int q0 = blockIdx.x * 128;

    const __nv_bfloat16* Qh = Qhi + (size_t)b * MSEQ * DPH;
    const __nv_bfloat16* Ql = Qlo + (size_t)b * MSEQ * DPH;
    const __nv_bfloat16* Kh = Khi + (size_t)b * MSEQ * DPH;
    const __nv_bfloat16* Kl = Klo + (size_t)b * MSEQ * DPH;
    const __nv_bfloat16* Vh = Vthi + (size_t)b * DPH * MSEQ;
    const __nv_bfloat16* Vl = Vtlo + (size_t)b * DPH * MSEQ;

    // ---- stage Q into smem (hi -> stage0 area, lo -> stage1 area) and frag ----
#pragma unroll
    for (int i = 0; i < 4; i++) {
        int chunk = i * 256 + tid;       // 1024 chunks: 128 rows x 8
        int row = chunk >> 3, c16 = chunk & 7;
        CP_ASYNC16(sbase + (uint32_t)(row * AP + c16 * 16),
                   Qh + (size_t)(q0 + row) * DPH + c16 * 8);
        CP_ASYNC16(sbase + A_STAGE + (uint32_t)(row * AP + c16 * 16),
                   Ql + (size_t)(q0 + row) * DPH + c16 * 8);
    }
    CP_COMMIT(); CP_WAIT0();
    __syncthreads();

    uint32_t qfh[16], qfl[16];
    {
        const uint32_t qa = sbase + (uint32_t)((wq * 16 + (lane & 15)) * AP + (lane >> 4) * 16);
#pragma unroll
        for (int s = 0; s < 4; s++) {
            LDM_X4(qfh + s * 4, qa + s * 32);
            LDM_X4(qfl + s * 4, qa + A_STAGE + s * 32);
        }
    }
    __syncthreads();   // all warps done reading Q smem before it's overwritten

    // ---- init static Vt rows 64-71 (ones row 64, zeros 65-71), both stages ----
    for (int i = tid; i < 8 * 72; i += 256) {
        int row = 64 + i / 72, col = i % 72;
        __nv_bfloat16 v = (row == 64 && col < 64) ? __float2bfloat16(1.0f)
                                                  : __float2bfloat16(0.0f);
        *(__nv_bfloat16*)(sm_raw + A_VHI + row * AP + col * 2) = v;
        *(__nv_bfloat16*)(sm_raw + A_STAGE + A_VHI + row * AP + col * 2) = v;
        *(__nv_bfloat16*)(sm_raw + A_VLO + row * AP + col * 2) = __float2bfloat16(0.0f);
        *(__nv_bfloat16*)(sm_raw + A_STAGE + A_VLO + row * AP + col * 2) = __float2bfloat16(0.0f);
    }

    // ---- per-thread state ----
    float acc[9][4];
#pragma unroll
    for (int j = 0; j < 9; j++)
#pragma unroll
        for (int e = 0; e < 4; e++) acc[j][e] = 0.0f;
    float m0r = 0.0f, m1r = 0.0f;    // scores >= 0 (relu6 inputs), so 0 is a valid init

    // lane maps (validated conventions)
    const uint32_t bmap = (uint32_t)(((lane & 7) + ((lane >> 4) & 1) * 8) * AP
                                     + ((lane >> 3) & 1) * 16);
    const int l15 = lane & 15;
    const uint32_t omap = (uint32_t)((64 + (l15 & 7)) * AP + ((l15 >> 3) & 1) * 16);

    auto load_tile = [&](int t) {
        const uint32_t sb = sbase + (t & 1) * A_STAGE;
        const int k0 = t * 64;
#pragma unroll
        for (int i = 0; i < 2; i++) {
            int chunk = i * 256 + tid;   // 512 chunks: 64 rows x 8
            int row = chunk >> 3, c16 = chunk & 7;
            size_t ko = (size_t)(k0 + row) * DPH + c16 * 8;      // K rows = kpos
            size_t vo = (size_t)row * MSEQ + k0 + c16 * 8;       // Vt rows = dph
            CP_ASYNC16(sb + A_KHI + (uint32_t)(row * AP + c16 * 16), Kh + ko);
            CP_ASYNC16(sb + A_KLO + (uint32_t)(row * AP + c16 * 16), Kl + ko);
            CP_ASYNC16(sb + A_VHI + (uint32_t)(row * AP + c16 * 16), Vh + vo);
            CP_ASYNC16(sb + A_VLO + (uint32_t)(row * AP + c16 * 16), Vl + vo);
        }
    };

    load_tile(0); CP_COMMIT();

    const int NT = MSEQ / 64;
    for (int t = 0; t < NT; t++) {
        if (t > 0) __syncthreads();           // everyone done with stage (t+1)&1
        if (t + 1 < NT) load_tile(t + 1);
        CP_COMMIT();
        if (t + 1 < NT) { CP_WAIT1(); } else { CP_WAIT0(); }
        __syncthreads();                      // tile t visible to all warps

        const uint32_t sb = sbase + (t & 1) * A_STAGE;

        // ---- S = Q @ K^T (3-pass split bf16) ----
        float S[8][4];
#pragma unroll
        for (int j = 0; j < 8; j++)
#pragma unroll
            for (int e = 0; e < 4; e++) S[j][e] = 0.0f;

#pragma unroll
        for (int s = 0; s < 4; s++) {
#pragma unroll
            for (int g = 0; g < 4; g++) {
                uint32_t bh[4], bl[4];
                const uint32_t ka = sb + bmap + (uint32_t)(g * 16 * AP + s * 32);
                LDM_X4(bh, ka + A_KHI);
                LDM_X4(bl, ka + A_KLO);
                MMA_BF16(S[g * 2],     qfh + s * 4, bh[0], bh[1]);
                MMA_BF16(S[g * 2 + 1], qfh + s * 4, bh[2], bh[3]);
                MMA_BF16(S[g * 2],     qfh + s * 4, bl[0], bl[1]);
                MMA_BF16(S[g * 2 + 1], qfh + s * 4, bl[2], bl[3]);
                MMA_BF16(S[g * 2],     qfl + s * 4, bh[0], bh[1]);
                MMA_BF16(S[g * 2 + 1], qfl + s * 4, bh[2], bh[3]);
            }
        }

        // ---- online softmax ----
        float t0 = S[0][0], t1 = S[0][2];
#pragma unroll
        for (int j = 0; j < 8; j++) {
            t0 = fmaxf(t0, fmaxf(S[j][0], S[j][1]));
            t1 = fmaxf(t1, fmaxf(S[j][2], S[j][3]));
        }
        t0 = fmaxf(t0, __shfl_xor_sync(0xffffffffu, t0, 1));
        t0 = fmaxf(t0, __shfl_xor_sync(0xffffffffu, t0, 2));
        t1 = fmaxf(t1, __shfl_xor_sync(0xffffffffu, t1, 1));
        t1 = fmaxf(t1, __shfl_xor_sync(0xffffffffu, t1, 2));
        float m0n = fmaxf(m0r, t0), m1n = fmaxf(m1r, t1);
        float c0 = __expf((m0r - m0n) * inv8);
        float c1 = __expf((m1r - m1n) * inv8);
        m0r = m0n; m1r = m1n;
        const float b0 = m0n * inv8, b1 = m1n * inv8;

        uint32_t pa[16];
#pragma unroll
        for (int j = 0; j < 8; j++) {
            float p00 = __expf(fmaf(S[j][0], inv8, -b0));
            float p01 = __expf(fmaf(S[j][1], inv8, -b0));
            float p10 = __expf(fmaf(S[j][2], inv8, -b1));
            float p11 = __expf(fmaf(S[j][3], inv8, -b1));
            int base = (j >> 1) * 4 + (j & 1) * 2;
            PACK_BF16X2(pa[base],     p00, p01);
            PACK_BF16X2(pa[base + 1], p10, p11);
        }
#pragma unroll
        for (int j = 0; j < 9; j++) {
            acc[j][0] *= c0; acc[j][1] *= c0;
            acc[j][2] *= c1; acc[j][3] *= c1;
        }

        // ---- PV (2-pass: P*Vhi + P*Vlo) + ones-row for l ----
#pragma unroll
        for (int s = 0; s < 4; s++) {
#pragma unroll
            for (int g = 0; g < 4; g++) {
                uint32_t vh[4], vl[4];
                const uint32_t va = sb + bmap + (uint32_t)(g * 16 * AP + s * 32);
                LDM_X4(vh, va + A_VHI);
                LDM_X4(vl, va + A_VLO);
                MMA_BF16(acc[g * 2],     pa + s * 4, vh[0], vh[1]);
                MMA_BF16(acc[g * 2 + 1], pa + s * 4, vh[2], vh[3]);
                MMA_BF16(acc[g * 2],     pa + s * 4, vl[0], vl[1]);
                MMA_BF16(acc[g * 2 + 1], pa + s * 4, vl[2], vl[3]);
            }
            uint32_t vo[2];
            LDM_X2(vo, sb + A_VHI + omap + (uint32_t)(s * 32));
            MMA_BF16(acc[8], pa + s * 4, vo[0], vo[1]);
        }
    }

    // ---- finalize: divide by l (ones-column), store bf16 hi/lo ----
    float l0 = __shfl_sync(0xffffffffu, acc[8][0], lane & ~3);
    float l1 = __shfl_sync(0xffffffffu, acc[8][2], lane & ~3);
    float inv0 = 1.0f / l0, inv1 = 1.0f / l1;

    const int ra = q0 + wq * 16 + (lane >> 2);
    const size_t toka = (size_t)(nb * MSEQ + ra) * DIM;
    const size_t tokb = toka + 8 * DIM;
#pragma unroll
    for (int j = 0; j < 8; j++) {
        int c = h * 64 + j * 8 + (lane & 3) * 2;
        float v0 = acc[j][0] * inv0, v1 = acc[j][1] * inv0;
        float v2 = acc[j][2] * inv1, v3 = acc[j][3] * inv1;
        __nv_bfloat16 h0 = __float2bfloat16(v0), h1 = __float2bfloat16(v1);
        __nv_bfloat16 h2 = __float2bfloat16(v2), h3 = __float2bfloat16(v3);
        uint32_t hp0 = (uint32_t)*(uint16_t*)&h0 | ((uint32_t)*(uint16_t*)&h1 << 16);
        uint32_t hp1 = (uint32_t)*(uint16_t*)&h2 | ((uint32_t)*(uint16_t*)&h3 << 16);
        uint32_t lp0, lp1;
        PACK_BF16X2(lp0, v0 - __bfloat162float(h0), v1 - __bfloat162float(h1));
        PACK_BF16X2(lp1, v2 - __bfloat162float(h2), v3 - __bfloat162float(h3));
        *(uint32_t*)(atthi + toka + c) = hp0;
        *(uint32_t*)(attlo + toka + c) = lp0;
        *(uint32_t*)(atthi + tokb + c) = hp1;
        *(uint32_t*)(attlo + tokb + c) = lp1;
    }
}

// ===========================================================================
// LayerNorm over last dim (1024). PAIR=1: bf16 hi/lo out; PAIR=0: fp32 out.
// ===========================================================================
template <int PAIR>
__global__ void __launch_bounds__(256) layernorm_rows(
    const float* __restrict__ X, const float* __restrict__ w,
    const float* __restrict__ bb, float* __restrict__ Yf,
    __nv_bfloat16* __restrict__ Yhi, __nv_bfloat16* __restrict__ Ylo)
{
    const int row = blockIdx.x;
    const float* x = X + (size_t)row * DIM;
    const int tid = threadIdx.x;

    float v[4];
    float s = 0.0f;
#pragma unroll
    for (int i = 0; i < 4; i++) {
        v[i] = x[i * 256 + tid];
        s += v[i];
    }

    __shared__ float red[256];
    red[tid] = s;
    __syncthreads();
#pragma unroll
    for (int st = 128; st >= 1; st >>= 1) {
        if (tid < st) red[tid] += red[tid + st];
        __syncthreads();
    }
    float mu = red[0] * (1.0f / DIM);
    __syncthreads();

    float vs = 0.0f;
#pragma unroll
    for (int i = 0; i < 4; i++) {
        float d = v[i] - mu;
        vs += d * d;
    }
    red[tid] = vs;
    __syncthreads();
#pragma unroll
    for (int st = 128; st >= 1; st >>= 1) {
        if (tid < st) red[tid] += red[tid + st];
        __syncthreads();
    }
    float var = red[0] * (1.0f / DIM);
    float inv = rsqrtf(var + 1e-5f);

#pragma unroll
    for (int i = 0; i < 4; i++) {
        int c = i * 256 + tid;
        float y = (v[i] - mu) * inv * w[c] + bb[c];
        if (PAIR) {
            __nv_bfloat16 hi = __float2bfloat16(y);
            size_t o = (size_t)row * DIM + c;
            Yhi[o] = hi;
            Ylo[o] = __float2bfloat16(y - __bfloat162float(hi));
        } else {
            Yf[(size_t)row * DIM + c] = y;
        }
    }
}

// ===========================================================================
// Launch
// ===========================================================================
extern "C" void kernel_launch(void* const* d_in, const int* in_sizes, int n_in,
                              void* d_out, int out_size)
{
    const float* x     = (const float*)d_in[0];
    const float* qvk_w = (const float*)d_in[1];
    const float* qvk_b = (const float*)d_in[2];
    const float* qh_w  = (const float*)d_in[3];
    const float* qh_b  = (const float*)d_in[4];
    const float* kh_w  = (const float*)d_in[5];
    const float* kh_b  = (const float*)d_in[6];
    const float* vh_w  = (const float*)d_in[7];
    const float* vh_b  = (const float*)d_in[8];
    const float* o_w   = (const float*)d_in[9];
    const float* o_b   = (const float*)d_in[10];
    const float* ln1_w = (const float*)d_in[11];
    const float* ln1_b = (const float*)d_in[12];
    const float* m1_w  = (const float*)d_in[13];
    const float* m1_b  = (const float*)d_in[14];
    const float* m2_w  = (const float*)d_in[15];
    const float* m2_b  = (const float*)d_in[16];
    const float* ln2_w = (const float*)d_in[17];
    const float* ln2_b = (const float*)d_in[18];
    float* out = (float*)d_out;

    float *t1, *t3;
    __nv_bfloat16 *xhi, *xlo, *qvkhi, *qvklo, *atthi, *attlo,
                  *ln1hi, *ln1lo, *m1hi, *m1lo;
    __nv_bfloat16 *Qhi, *Qlo, *Khi, *Klo, *Vthi, *Vtlo;
    __nv_bfloat16 *wqvkhi, *wqvklo, *wqhi, *wqlo, *wkhi, *wklo,
                  *wvhi, *wvlo, *wohi, *wolo, *wm1hi, *wm1lo, *wm2hi, *wm2lo;

    cudaGetSymbolAddress((void**)&t1,  g_t1);
    cudaGetSymbolAddress((void**)&t3,  g_t3);
    cudaGetSymbolAddress((void**)&xhi, g_xhi);     cudaGetSymbolAddress((void**)&xlo, g_xlo);
    cudaGetSymbolAddress((void**)&qvkhi, g_qvkhi); cudaGetSymbolAddress((void**)&qvklo, g_qvklo);
    cudaGetSymbolAddress((void**)&atthi, g_atthi); cudaGetSymbolAddress((void**)&attlo, g_attlo);
    cudaGetSymbolAddress((void**)&ln1hi, g_ln1hi); cudaGetSymbolAddress((void**)&ln1lo, g_ln1lo);
    cudaGetSymbolAddress((void**)&m1hi, g_m1hi);   cudaGetSymbolAddress((void**)&m1lo, g_m1lo);
    cudaGetSymbolAddress((void**)&Qhi, g_Qhi);     cudaGetSymbolAddress((void**)&Qlo, g_Qlo);
    cudaGetSymbolAddress((void**)&Khi, g_Khi);     cudaGetSymbolAddress((void**)&Klo, g_Klo);
    cudaGetSymbolAddress((void**)&Vthi, g_Vthi);   cudaGetSymbolAddress((void**)&Vtlo, g_Vtlo);
    cudaGetSymbolAddress((void**)&wqvkhi, g_wqvkhi); cudaGetSymbolAddress((void**)&wqvklo, g_wqvklo);
    cudaGetSymbolAddress((void**)&wqhi, g_wqhi);   cudaGetSymbolAddress((void**)&wqlo, g_wqlo);
    cudaGetSymbolAddress((void**)&wkhi, g_wkhi);   cudaGetSymbolAddress((void**)&wklo, g_wklo);
    cudaGetSymbolAddress((void**)&wvhi, g_wvhi);   cudaGetSymbolAddress((void**)&wvlo, g_wvlo);
    cudaGetSymbolAddress((void**)&wohi, g_wohi);   cudaGetSymbolAddress((void**)&wolo, g_wolo);
    cudaGetSymbolAddress((void**)&wm1hi, g_wm1hi); cudaGetSymbolAddress((void**)&wm1lo, g_wm1lo);
    cudaGetSymbolAddress((void**)&wm2hi, g_wm2hi); cudaGetSymbolAddress((void**)&wm2lo, g_wm2lo);

    cudaFuncSetAttribute(gemm_mma,
                         cudaFuncAttributeMaxDynamicSharedMemorySize, GEMM_SMEM);
    cudaFuncSetAttribute(attn_mma,
                         cudaFuncAttributeMaxDynamicSharedMemorySize, ATTN_SMEM);

    const dim3 thr(256);
    const float inv8 = 1.0f / (sqrtf((float)DPH) + 1e-10f);

    // --- weight transpose + split ---
    transpose_split<<<dim3(DH3 / 32, DIM / 32), thr>>>(qvk_w, DIM, DH3, wqvkhi, wqvklo);
    transpose_split<<<dim3(DIM / 32, DIM / 32), thr>>>(qh_w, DIM, DIM, wqhi, wqlo);
    transpose_split<<<dim3(DIM / 32, DIM / 32), thr>>>(kh_w, DIM, DIM, wkhi, wklo);
    transpose_split<<<dim3(DIM / 32, DIM / 32), thr>>>(vh_w, DIM, DIM, wvhi, wvlo);
    transpose_split<<<dim3(DIM / 32, DIM / 32), thr>>>(o_w,  DIM, DIM, wohi, wolo);
    transpose_split<<<dim3(DEXP / 32, DIM / 32), thr>>>(m1_w, DIM, DEXP, wm1hi, wm1lo);
    transpose_split<<<dim3(DIM / 32, DEXP / 32), thr>>>(m2_w, DEXP, DIM, wm2hi, wm2lo);

    split_pair<<<TTOK * DIM / 1024, thr>>>(x, xhi, xlo);

    // 1. qvk projection -> bf16 pair
    gemm_mma<<<dim3(DH3 / BN, TTOK / BM), thr, GEMM_SMEM>>>(
        xhi, xlo, DIM, wqvkhi, wqvklo, qvk_b,
        nullptr, qvkhi, qvklo, DH3, DIM, OUT_PAIR);

    // 2. Q/K head projections -> bf16 pair [b][m][64]; V -> [b][dph][m]
    gemm_mma<<<dim3(DIM / BN, TTOK / BM), thr, GEMM_SMEM>>>(
        qvkhi,            qvklo,            DH3, wqhi, wqlo, qh_b,
        nullptr, Qhi, Qlo, 0, DIM, OUT_QKPAIR);
    gemm_mma<<<dim3(DIM / BN, TTOK / BM), thr, GEMM_SMEM>>>(
        qvkhi + DIM,      qvklo + DIM,      DH3, wkhi, wklo, kh_b,
        nullptr, Khi, Klo, 0, DIM, OUT_QKPAIR);
    gemm_mma<<<dim3(DIM / BN, TTOK / BM), thr, GEMM_SMEM>>>(
        qvkhi + 2 * DIM,  qvklo + 2 * DIM,  DH3, wvhi, wvlo, vh_b,
        nullptr, Vthi, Vtlo, 0, DIM, OUT_VT);

    // 3-5. Flash attention on tensor cores
    attn_mma<<<dim3(MSEQ / 128, NB * NH), thr, ATTN_SMEM>>>(
        Qhi, Qlo, Khi, Klo, Vthi, Vtlo, atthi, attlo, inv8);

    // 6. O projection
    gemm_mma<<<dim3(DIM / BN, TTOK / BM), thr, GEMM_SMEM>>>(
        atthi, attlo, DIM, wohi, wolo, o_b,
        t1, nullptr, nullptr, DIM, DIM, OUT_F32);

    // 7. LN1 -> bf16 pair
    layernorm_rows<1><<<TTOK, thr>>>(t1, ln1_w, ln1_b, nullptr, ln1hi, ln1lo);

    // 8. m1 -> bf16 pair
    gemm_mma<<<dim3(DEXP / BN, TTOK / BM), thr, GEMM_SMEM>>>(
        ln1hi, ln1lo, DIM, wm1hi, wm1lo, m1_b,
        nullptr, m1hi, m1lo, DEXP, DIM, OUT_PAIR);

    // 9. m2 -> fp32
    gemm_mma<<<dim3(DIM / BN, TTOK / BM), thr, GEMM_SMEM>>>(
        m1hi, m1lo, DEXP, wm2hi, wm2lo, m2_b,
        t3, nullptr, nullptr, DIM, DEXP, OUT_F32);

    // 10. LN2 -> out
    layernorm_rows<0><<<TTOK, thr>>>(t3, ln2_w, ln2_b, out, nullptr, nullptr);
}

// round 8
// speedup vs baseline: 2.7287x; 1.2479x over previous
#include <cuda_runtime.h>
#include <cuda_bf16.h>
#include <math.h>
#include <stdint.h>

// Problem constants
#define NB    2
#define MSEQ  2048
#define DIM   1024
#define NH    16
#define DPH   64
#define TTOK  (NB * MSEQ)      // 4096 tokens
#define DH3   (3 * DIM)        // 3072
#define DEXP  (2 * DIM)        // 2048

// ===========================================================================
// PTX helpers (base-target sm_80-class only)
// ===========================================================================
__device__ __forceinline__ uint32_t smem_to_u32(const void* smem_ptr) {
    uint32_t addr;
    asm("{ .reg .u64 tmp; cvta.to.shared.u64 tmp, %1; cvt.u32.u64 %0, tmp; }"
        : "=r"(addr) : "l"(smem_ptr));
    return addr;
}

#define CP_ASYNC16(dst_u32, src_ptr) \
    asm volatile("cp.async.cg.shared.global [%0], [%1], 16;" \
        :: "r"(dst_u32), "l"(src_ptr) : "memory")

#define CP_COMMIT() asm volatile("cp.async.commit_group;" ::: "memory")
#define CP_WAIT1()  asm volatile("cp.async.wait_group 1;" ::: "memory")
#define CP_WAIT0()  asm volatile("cp.async.wait_group 0;" ::: "memory")

#define LDM_X4(R, addr) \
    asm volatile("ldmatrix.sync.aligned.m8n8.x4.shared.b16 {%0,%1,%2,%3}, [%4];" \
        : "=r"((R)[0]), "=r"((R)[1]), "=r"((R)[2]), "=r"((R)[3]) : "r"(addr))

#define LDM_X2(R, addr) \
    asm volatile("ldmatrix.sync.aligned.m8n8.x2.shared.b16 {%0,%1}, [%2];" \
        : "=r"((R)[0]), "=r"((R)[1]) : "r"(addr))

#define MMA_BF16(D, A, B0, B1) \
    asm volatile("mma.sync.aligned.m16n8k16.row.col.f32.bf16.bf16.f32 " \
        "{%0,%1,%2,%3}, {%4,%5,%6,%7}, {%8,%9}, {%0,%1,%2,%3};" \
        : "+f"((D)[0]), "+f"((D)[1]), "+f"((D)[2]), "+f"((D)[3]) \
        : "r"((A)[0]), "r"((A)[1]), "r"((A)[2]), "r"((A)[3]), "r"(B0), "r"(B1))

// pack two fp32 -> bf16x2 (lo half from first value)
#define PACK_BF16X2(r, vlo, vhi) \
    asm("cvt.rn.bf16x2.f32 %0, %1, %2;" : "=r"(r) : "f"(vhi), "f"(vlo))

// ===========================================================================
// Scratch (allocation-free: __device__ globals)
// ===========================================================================
__device__ float g_t1[TTOK * DIM];
__device__ float g_t3[TTOK * DIM];
__device__ __nv_bfloat16 g_xhi[TTOK * DIM],  g_xlo[TTOK * DIM];
__device__ __nv_bfloat16 g_qvkhi[TTOK * DH3], g_qvklo[TTOK * DH3];
__device__ __nv_bfloat16 g_atthi[TTOK * DIM], g_attlo[TTOK * DIM];
__device__ __nv_bfloat16 g_ln1hi[TTOK * DIM], g_ln1lo[TTOK * DIM];
__device__ __nv_bfloat16 g_m1hi[TTOK * DEXP], g_m1lo[TTOK * DEXP];
__device__ __nv_bfloat16 g_Qhi[NB * NH * MSEQ * DPH], g_Qlo[NB * NH * MSEQ * DPH];   // [b][m][64]
__device__ __nv_bfloat16 g_Khi[NB * NH * MSEQ * DPH], g_Klo[NB * NH * MSEQ * DPH];   // [b][m][64]
__device__ __nv_bfloat16 g_Vthi[NB * NH * DPH * MSEQ], g_Vtlo[NB * NH * DPH * MSEQ]; // [b][dph][m]
__device__ __nv_bfloat16 g_wqvkhi[DH3 * DIM], g_wqvklo[DH3 * DIM];
__device__ __nv_bfloat16 g_wqhi[DIM * DIM],   g_wqlo[DIM * DIM];
__device__ __nv_bfloat16 g_wkhi[DIM * DIM],   g_wklo[DIM * DIM];
__device__ __nv_bfloat16 g_wvhi[DIM * DIM],   g_wvlo[DIM * DIM];
__device__ __nv_bfloat16 g_wohi[DIM * DIM],   g_wolo[DIM * DIM];
__device__ __nv_bfloat16 g_wm1hi[DEXP * DIM], g_wm1lo[DEXP * DIM];
__device__ __nv_bfloat16 g_wm2hi[DIM * DEXP], g_wm2lo[DIM * DEXP];

__device__ __forceinline__ float relu6f(float v) {
    return fminf(fmaxf(v, 0.0f), 6.0f);
}

// ===========================================================================
// Batched preprocessing: 7 weight transposes + input split in ONE launch.
// Job table constant-folded; 1D grid of 15360 blocks.
// ===========================================================================
__device__ __forceinline__ void trans_body(
    const float* __restrict__ W, int Kdim, int Ndim,
    __nv_bfloat16* __restrict__ Thi, __nv_bfloat16* __restrict__ Tlo, int l)
{
    __shared__ float t[32][33];
    const int bx = l % (Ndim / 32), by = l / (Ndim / 32);
    const int k0 = by * 32, n0 = bx * 32;
    const int tx = threadIdx.x & 31, ty = threadIdx.x >> 5;
#pragma unroll
    for (int j = 0; j < 4; j++)
        t[ty + 8 * j][tx] = W[(size_t)(k0 + ty + 8 * j) * Ndim + n0 + tx];
    __syncthreads();
#pragma unroll
    for (int j = 0; j < 4; j++) {
        float v = t[tx][ty + 8 * j];
        __nv_bfloat16 hi = __float2bfloat16(v);
        size_t o = (size_t)(n0 + ty + 8 * j) * Kdim + k0 + tx;
        Thi[o] = hi;
        Tlo[o] = __float2bfloat16(v - __bfloat162float(hi));
    }
}

__global__ void __launch_bounds__(256) batched_pre(
    const float* __restrict__ qvk_w, const float* __restrict__ qh_w,
    const float* __restrict__ kh_w,  const float* __restrict__ vh_w,
    const float* __restrict__ o_w,   const float* __restrict__ m1_w,
    const float* __restrict__ m2_w,  const float* __restrict__ x,
    __nv_bfloat16* wqvkhi, __nv_bfloat16* wqvklo,
    __nv_bfloat16* wqhi, __nv_bfloat16* wqlo,
    __nv_bfloat16* wkhi, __nv_bfloat16* wklo,
    __nv_bfloat16* wvhi, __nv_bfloat16* wvlo,
    __nv_bfloat16* wohi, __nv_bfloat16* wolo,
    __nv_bfloat16* wm1hi, __nv_bfloat16* wm1lo,
    __nv_bfloat16* wm2hi, __nv_bfloat16* wm2lo,
    __nv_bfloat16* xhi, __nv_bfloat16* xlo)
{
    const int b = blockIdx.x;
    if (b < 3072)       trans_body(qvk_w, DIM, DH3, wqvkhi, wqvklo, b);
    else if (b < 4096)  trans_body(qh_w, DIM, DIM, wqhi, wqlo, b - 3072);
    else if (b < 5120)  trans_body(kh_w, DIM, DIM, wkhi, wklo, b - 4096);
    else if (b < 6144)  trans_body(vh_w, DIM, DIM, wvhi, wvlo, b - 5120);
    else if (b < 7168)  trans_body(o_w,  DIM, DIM, wohi, wolo, b - 6144);
    else if (b < 9216)  trans_body(m1_w, DIM, DEXP, wm1hi, wm1lo, b - 7168);
    else if (b < 11264) trans_body(m2_w, DEXP, DIM, wm2hi, wm2lo, b - 9216);
    else {
        int i4 = (b - 11264) * 256 + threadIdx.x;
        float4 v = ((const float4*)x)[i4];
        float vv[4] = {v.x, v.y, v.z, v.w};
#pragma unroll
        for (int j = 0; j < 4; j++) {
            __nv_bfloat16 hi = __float2bfloat16(vv[j]);
            xhi[i4 * 4 + j] = hi;
            xlo[i4 * 4 + j] = __float2bfloat16(vv[j] - __bfloat162float(hi));
        }
    }
}
#define PRE_BLOCKS 15360

// ===========================================================================
// mma.sync split-bf16 GEMM: C = relu6(A[M,K] @ B^T[N,K] + bias)
// 2-stage cp.async pipeline (2 CTAs/SM), smem-staged permuted epilogues.
// ===========================================================================
#define BM 128
#define BN 128
#define BK 32
#define ROWB 80
#define TILE_SZ  (128 * ROWB)        // 10240
#define STAGE_SZ (4 * TILE_SZ)       // 40960
#define GEMM_SMEM (2 * STAGE_SZ)     // 81920  (also covers 69632B staging)
#define STG_PITCH 136                 // staging pitch in bf16 elements

#define OUT_F32    0
#define OUT_PAIR   1
#define OUT_QKPAIR 2   // bf16 hi/lo head-scatter  [b][m][64]
#define OUT_VT     3   // bf16 hi/lo transposed    [b][dph][m]

__global__ void __launch_bounds__(256) gemm_mma(
    const __nv_bfloat16* __restrict__ Ahi, const __nv_bfloat16* __restrict__ Alo, int lda,
    const __nv_bfloat16* __restrict__ Bhi, const __nv_bfloat16* __restrict__ Blo,
    const float* __restrict__ bias,
    float* __restrict__ Cf,
    __nv_bfloat16* __restrict__ Chi, __nv_bfloat16* __restrict__ Clo,
    int ldc, int K, int mode)
{
    extern __shared__ char sm_raw[];
    const uint32_t sbase = smem_to_u32(sm_raw);
    const int tid  = threadIdx.x;
    const int lane = tid & 31;
    const int wid  = tid >> 5;
    const int wr   = wid & 3;
    const int wc   = wid >> 2;
    const int m0   = blockIdx.y * BM;
    const int n0   = blockIdx.x * BN;

    float acc[2][8][4];
#pragma unroll
    for (int i = 0; i < 2; i++)
#pragma unroll
        for (int j = 0; j < 8; j++)
#pragma unroll
            for (int e = 0; e < 4; e++) acc[i][j][e] = 0.0f;

    auto load_chunk = [&](int c) {
        const uint32_t sb = sbase + (c & 1) * STAGE_SZ;
#pragma unroll
        for (int t = 0; t < 8; t++) {
            const int tile  = t >> 1;
            const int chunk = (t & 1) * 256 + tid;
            const int row   = chunk >> 2;
            const int col   = chunk & 3;
            const __nv_bfloat16* src;
            if (tile == 0)
                src = Ahi + (size_t)(m0 + row) * lda + c * BK + col * 8;
            else if (tile == 1)
                src = Alo + (size_t)(m0 + row) * lda + c * BK + col * 8;
            else if (tile == 2)
                src = Bhi + (size_t)(n0 + row) * K + c * BK + col * 8;
            else
                src = Blo + (size_t)(n0 + row) * K + c * BK + col * 8;
            CP_ASYNC16(sb + tile * TILE_SZ + (uint32_t)(row * ROWB + col * 16), src);
        }
    };

    auto compute = [&](int c) {
        const uint32_t sb = sbase + (c & 1) * STAGE_SZ;
        const uint32_t aB = sb + (uint32_t)((wr * 32 + (lane & 15)) * ROWB + (lane >> 4) * 16);
        const uint32_t bB = sb + 2 * TILE_SZ
            + (uint32_t)((wc * 64 + (lane & 7) + ((lane >> 4) & 1) * 8) * ROWB
                         + ((lane >> 3) & 1) * 16);
#pragma unroll
        for (int s = 0; s < 2; s++) {
            uint32_t ah[2][4], al[2][4];
#pragma unroll
            for (int i = 0; i < 2; i++) {
                LDM_X4(ah[i], aB + (uint32_t)(i * 16 * ROWB + s * 32));
                LDM_X4(al[i], aB + TILE_SZ + (uint32_t)(i * 16 * ROWB + s * 32));
            }
#pragma unroll
            for (int jj = 0; jj < 4; jj++) {
                uint32_t bh[4], bl[4];
                LDM_X4(bh, bB + (uint32_t)(jj * 16 * ROWB + s * 32));
                LDM_X4(bl, bB + TILE_SZ + (uint32_t)(jj * 16 * ROWB + s * 32));
#pragma unroll
                for (int i = 0; i < 2; i++) {
                    MMA_BF16(acc[i][jj * 2],     ah[i], bh[0], bh[1]);
                    MMA_BF16(acc[i][jj * 2 + 1], ah[i], bh[2], bh[3]);
                    MMA_BF16(acc[i][jj * 2],     ah[i], bl[0], bl[1]);
                    MMA_BF16(acc[i][jj * 2 + 1], ah[i], bl[2], bl[3]);
                    MMA_BF16(acc[i][jj * 2],     al[i], bh[0], bh[1]);
                    MMA_BF16(acc[i][jj * 2 + 1], al[i], bh[2], bh[3]);
                }
            }
        }
    };

    const int nchunk = K / BK;
    load_chunk(0); CP_COMMIT();

    for (int c = 0; c < nchunk; c++) {
        if (c > 0) __syncthreads();           // buffer (c+1)&1 free (compute c-1 done)
        if (c + 1 < nchunk) load_chunk(c + 1);
        CP_COMMIT();
        if (c + 1 < nchunk) { CP_WAIT1(); } else { CP_WAIT0(); }
        __syncthreads();                      // tile c visible
        compute(c);
    }

    // ================= epilogue =================
    if (mode == OUT_F32 || mode == OUT_PAIR) {
#pragma unroll
        for (int i = 0; i < 2; i++) {
            const int r0 = m0 + wr * 32 + i * 16 + (lane >> 2);
#pragma unroll
            for (int jf = 0; jf < 8; jf++) {
                const int c0 = n0 + wc * 64 + jf * 8 + (lane & 3) * 2;
#pragma unroll
                for (int half = 0; half < 2; half++) {
                    const int m = r0 + half * 8;
                    float v0 = relu6f(acc[i][jf][half * 2]     + bias[c0]);
                    float v1 = relu6f(acc[i][jf][half * 2 + 1] + bias[c0 + 1]);
                    if (mode == OUT_F32) {
                        *(float2*)(Cf + (size_t)m * ldc + c0) = make_float2(v0, v1);
                    } else {
                        __nv_bfloat16 h0 = __float2bfloat16(v0), h1 = __float2bfloat16(v1);
                        uint32_t hp = (uint32_t)*(uint16_t*)&h0
                                    | ((uint32_t)*(uint16_t*)&h1 << 16);
                        uint32_t lp;
                        PACK_BF16X2(lp, v0 - __bfloat162float(h0), v1 - __bfloat162float(h1));
                        *(uint32_t*)(Chi + (size_t)m * ldc + c0) = hp;
                        *(uint32_t*)(Clo + (size_t)m * ldc + c0) = lp;
                    }
                }
            }
        }
    } else {
        // ---- staged permuted epilogue (OUT_QKPAIR / OUT_VT) ----
        __syncthreads();   // all warps done reading pipeline smem
        __nv_bfloat16* shi = (__nv_bfloat16*)sm_raw;
        __nv_bfloat16* slo = shi + 128 * STG_PITCH;
#pragma unroll
        for (int i = 0; i < 2; i++) {
            const int r0l = wr * 32 + i * 16 + (lane >> 2);   // local row 0..127
#pragma unroll
            for (int jf = 0; jf < 8; jf++) {
                const int c0 = wc * 64 + jf * 8 + (lane & 3) * 2;  // local col
#pragma unroll
                for (int e = 0; e < 4; e++) {
                    const int mml = r0l + (e >> 1) * 8;
                    const int nl  = c0 + (e & 1);
                    const int n   = n0 + nl;
                    float v = relu6f(acc[i][jf][e] + bias[n]);
                    __nv_bfloat16 hi = __float2bfloat16(v);
                    __nv_bfloat16 lo = __float2bfloat16(v - __bfloat162float(hi));
                    const int perm = (n & 15) * 8 + ((n >> 4) & 7);  // h*8+dphl
                    int a;
                    if (mode == OUT_QKPAIR) a = mml * STG_PITCH + perm;
                    else                    a = perm * STG_PITCH + mml;
                    shi[a] = hi;
                    slo[a] = lo;
                }
            }
        }
        __syncthreads();
        // coalesced 16B chunk stores: 2048 chunks per array
        const int dph0 = n0 >> 4;
#pragma unroll
        for (int it = 0; it < 8; it++) {
            const int ch = it * 256 + tid;
            uint4 vh, vl;
            size_t go;
            if (mode == OUT_QKPAIR) {
                const int mml = ch >> 4, h = ch & 15;
                vh = *(const uint4*)(shi + mml * STG_PITCH + h * 8);
                vl = *(const uint4*)(slo + mml * STG_PITCH + h * 8);
                const int mg = m0 + mml;
                const int nb = mg >> 11, mm = mg & 2047;
                go = ((((size_t)(nb * 16 + h) * 2048) + mm) * 64) + dph0;
            } else {
                const int row = ch >> 4, mmb = ch & 15;   // row = h*8+dphl
                vh = *(const uint4*)(shi + row * STG_PITCH + mmb * 8);
                vl = *(const uint4*)(slo + row * STG_PITCH + mmb * 8);
                const int h = row >> 3, dph = dph0 + (row & 7);
                const int nb = m0 >> 11;
                go = (((size_t)(nb * 16 + h) * 64) + dph) * 2048 + (m0 & 2047) + mmb * 8;
            }
            *(uint4*)(Chi + go) = vh;
            *(uint4*)(Clo + go) = vl;
        }
    }
}

// ===========================================================================
// Flash attention on mma.sync (split-bf16) — validated in R7.
// ===========================================================================
#define AP 144
#define A_KHI  0
#define A_KLO  (64 * AP)
#define A_VHI  (2 * 64 * AP)
#define A_VLO  (A_VHI + 72 * AP)
#define A_STAGE (A_VLO + 72 * AP)
#define ATTN_SMEM (2 * A_STAGE)

__global__ void __launch_bounds__(256) attn_mma(
    const __nv_bfloat16* __restrict__ Qhi, const __nv_bfloat16* __restrict__ Qlo,
    const __nv_bfloat16* __restrict__ Khi, const __nv_bfloat16* __restrict__ Klo,
    const __nv_bfloat16* __restrict__ Vthi, const __nv_bfloat16* __restrict__ Vtlo,
    __nv_bfloat16* __restrict__ atthi, __nv_bfloat16* __restrict__ attlo,
    float inv8)
{
    extern __shared__ char sm_raw[];
    const uint32_t sbase = smem_to_u32(sm_raw);
    const int tid = threadIdx.x;
    const int lane = tid & 31;
    const int wq = tid >> 5;
    const int b = blockIdx.y;
    const int nb = b >> 4, h = b & 15;
    const int q0 = blockIdx.x * 128;

    const __nv_bfloat16* Qh = Qhi + (size_t)b * MSEQ * DPH;
    const __nv_bfloat16* Ql = Qlo + (size_t)b * MSEQ * DPH;
    const __nv_bfloat16* Kh = Khi + (size_t)b * MSEQ * DPH;
    const __nv_bfloat16* Kl = Klo + (size_t)b * MSEQ * DPH;
    const __nv_bfloat16* Vh = Vthi + (size_t)b * DPH * MSEQ;
    const __nv_bfloat16* Vl = Vtlo + (size_t)b * DPH * MSEQ;

#pragma unroll
    for (int i = 0; i < 4; i++) {
        int chunk = i * 256 + tid;
        int row = chunk >> 3, c16 = chunk & 7;
        CP_ASYNC16(sbase + (uint32_t)(row * AP + c16 * 16),
                   Qh + (size_t)(q0 + row) * DPH + c16 * 8);
        CP_ASYNC16(sbase + A_STAGE + (uint32_t)(row * AP + c16 * 16),
                   Ql + (size_t)(q0 + row) * DPH + c16 * 8);
    }
    CP_COMMIT(); CP_WAIT0();
    __syncthreads();

    uint32_t qfh[16], qfl[16];
    {
        const uint32_t qa = sbase + (uint32_t)((wq * 16 + (lane & 15)) * AP + (lane >> 4) * 16);
#pragma unroll
        for (int s = 0; s < 4; s++) {
            LDM_X4(qfh + s * 4, qa + s * 32);
            LDM_X4(qfl + s * 4, qa + A_STAGE + s * 32);
        }
    }
    __syncthreads();

    for (int i = tid; i < 8 * 72; i += 256) {
        int row = 64 + i / 72, col = i % 72;
        __nv_bfloat16 v = (row == 64 && col < 64) ? __float2bfloat16(1.0f)
                                                  : __float2bfloat16(0.0f);
        *(__nv_bfloat16*)(sm_raw + A_VHI + row * AP + col * 2) = v;
        *(__nv_bfloat16*)(sm_raw + A_STAGE + A_VHI + row * AP + col * 2) = v;
        *(__nv_bfloat16*)(sm_raw + A_VLO + row * AP + col * 2) = __float2bfloat16(0.0f);
        *(__nv_bfloat16*)(sm_raw + A_STAGE + A_VLO + row * AP + col * 2) = __float2bfloat16(0.0f);
    }

    float acc[9][4];
#pragma unroll
    for (int j = 0; j < 9; j++)
#pragma unroll
        for (int e = 0; e < 4; e++) acc[j][e] = 0.0f;
    float m0r = 0.0f, m1r = 0.0f;

    const uint32_t bmap = (uint32_t)(((lane & 7) + ((lane >> 4) & 1) * 8) * AP
                                     + ((lane >> 3) & 1) * 16);
    const int l15 = lane & 15;
    const uint32_t omap = (uint32_t)((64 + (l15 & 7)) * AP + ((l15 >> 3) & 1) * 16);

    auto load_tile = [&](int t) {
        const uint32_t sb = sbase + (t & 1) * A_STAGE;
        const int k0 = t * 64;
#pragma unroll
        for (int i = 0; i < 2; i++) {
            int chunk = i * 256 + tid;
            int row = chunk >> 3, c16 = chunk & 7;
            size_t ko = (size_t)(k0 + row) * DPH + c16 * 8;
            size_t vo = (size_t)row * MSEQ + k0 + c16 * 8;
            CP_ASYNC16(sb + A_KHI + (uint32_t)(row * AP + c16 * 16), Kh + ko);
            CP_ASYNC16(sb + A_KLO + (uint32_t)(row * AP + c16 * 16), Kl + ko);
            CP_ASYNC16(sb + A_VHI + (uint32_t)(row * AP + c16 * 16), Vh + vo);
            CP_ASYNC16(sb + A_VLO + (uint32_t)(row * AP + c16 * 16), Vl + vo);
        }
    };

    load_tile(0); CP_COMMIT();

    const int NT = MSEQ / 64;
    for (int t = 0; t < NT; t++) {
        if (t > 0) __syncthreads();
        if (t + 1 < NT) load_tile(t + 1);
        CP_COMMIT();
        if (t + 1 < NT) { CP_WAIT1(); } else { CP_WAIT0(); }
        __syncthreads();

        const uint32_t sb = sbase + (t & 1) * A_STAGE;

        float S[8][4];
#pragma unroll
        for (int j = 0; j < 8; j++)
#pragma unroll
            for (int e = 0; e < 4; e++) S[j][e] = 0.0f;

#pragma unroll
        for (int s = 0; s < 4; s++) {
#pragma unroll
            for (int g = 0; g < 4; g++) {
                uint32_t bh[4], bl[4];
                const uint32_t ka = sb + bmap + (uint32_t)(g * 16 * AP + s * 32);
                LDM_X4(bh, ka + A_KHI);
                LDM_X4(bl, ka + A_KLO);
                MMA_BF16(S[g * 2],     qfh + s * 4, bh[0], bh[1]);
                MMA_BF16(S[g * 2 + 1], qfh + s * 4, bh[2], bh[3]);
                MMA_BF16(S[g * 2],     qfh + s * 4, bl[0], bl[1]);
                MMA_BF16(S[g * 2 + 1], qfh + s * 4, bl[2], bl[3]);
                MMA_BF16(S[g * 2],     qfl + s * 4, bh[0], bh[1]);
                MMA_BF16(S[g * 2 + 1], qfl + s * 4, bh[2], bh[3]);
            }
        }

        float t0 = S[0][0], t1 = S[0][2];
#pragma unroll
        for (int j = 0; j < 8; j++) {
            t0 = fmaxf(t0, fmaxf(S[j][0], S[j][1]));
            t1 = fmaxf(t1, fmaxf(S[j][2], S[j][3]));
        }
        t0 = fmaxf(t0, __shfl_xor_sync(0xffffffffu, t0, 1));
        t0 = fmaxf(t0, __shfl_xor_sync(0xffffffffu, t0, 2));
        t1 = fmaxf(t1, __shfl_xor_sync(0xffffffffu, t1, 1));
        t1 = fmaxf(t1, __shfl_xor_sync(0xffffffffu, t1, 2));
        float m0n = fmaxf(m0r, t0), m1n = fmaxf(m1r, t1);
        float c0 = __expf((m0r - m0n) * inv8);
        float c1 = __expf((m1r - m1n) * inv8);
        m0r = m0n; m1r = m1n;
        const float b0 = m0n * inv8, b1 = m1n * inv8;

        uint32_t pa[16];
#pragma unroll
        for (int j = 0; j < 8; j++) {
            float p00 = __expf(fmaf(S[j][0], inv8, -b0));
            float p01 = __expf(fmaf(S[j][1], inv8, -b0));
            float p10 = __expf(fmaf(S[j][2], inv8, -b1));
            float p11 = __expf(fmaf(S[j][3], inv8, -b1));
            int base = (j >> 1) * 4 + (j & 1) * 2;
            PACK_BF16X2(pa[base],     p00, p01);
            PACK_BF16X2(pa[base + 1], p10, p11);
        }
#pragma unroll
        for (int j = 0; j < 9; j++) {
            acc[j][0] *= c0; acc[j][1] *= c0;
            acc[j][2] *= c1; acc[j][3] *= c1;
        }

#pragma unroll
        for (int s = 0; s < 4; s++) {
#pragma unroll
            for (int g = 0; g < 4; g++) {
                uint32_t vh[4], vl[4];
                const uint32_t va = sb + bmap + (uint32_t)(g * 16 * AP + s * 32);
                LDM_X4(vh, va + A_VHI);
                LDM_X4(vl, va + A_VLO);
                MMA_BF16(acc[g * 2],     pa + s * 4, vh[0], vh[1]);
                MMA_BF16(acc[g * 2 + 1], pa + s * 4, vh[2], vh[3]);
                MMA_BF16(acc[g * 2],     pa + s * 4, vl[0], vl[1]);
                MMA_BF16(acc[g * 2 + 1], pa + s * 4, vl[2], vl[3]);
            }
            uint32_t vo[2];
            LDM_X2(vo, sb + A_VHI + omap + (uint32_t)(s * 32));
            MMA_BF16(acc[8], pa + s * 4, vo[0], vo[1]);
        }
    }

    float l0 = __shfl_sync(0xffffffffu, acc[8][0], lane & ~3);
    float l1 = __shfl_sync(0xffffffffu, acc[8][2], lane & ~3);
    float inv0 = 1.0f / l0, inv1 = 1.0f / l1;

    const int ra = q0 + wq * 16 + (lane >> 2);
    const size_t toka = (size_t)(nb * MSEQ + ra) * DIM;
    const size_t tokb = toka + 8 * DIM;
#pragma unroll
    for (int j = 0; j < 8; j++) {
        int c = h * 64 + j * 8 + (lane & 3) * 2;
        float v0 = acc[j][0] * inv0, v1 = acc[j][1] * inv0;
        float v2 = acc[j][2] * inv1, v3 = acc[j][3] * inv1;
        __nv_bfloat16 h0 = __float2bfloat16(v0), h1 = __float2bfloat16(v1);
        __nv_bfloat16 h2 = __float2bfloat16(v2), h3 = __float2bfloat16(v3);
        uint32_t hp0 = (uint32_t)*(uint16_t*)&h0 | ((uint32_t)*(uint16_t*)&h1 << 16);
        uint32_t hp1 = (uint32_t)*(uint16_t*)&h2 | ((uint32_t)*(uint16_t*)&h3 << 16);
        uint32_t lp0, lp1;
        PACK_BF16X2(lp0, v0 - __bfloat162float(h0), v1 - __bfloat162float(h1));
        PACK_BF16X2(lp1, v2 - __bfloat162float(h2), v3 - __bfloat162float(h3));
        *(uint32_t*)(atthi + toka + c) = hp0;
        *(uint32_t*)(attlo + toka + c) = lp0;
        *(uint32_t*)(atthi + tokb + c) = hp1;
        *(uint32_t*)(attlo + tokb + c) = lp1;
    }
}

// ===========================================================================
// LayerNorm over last dim (1024). PAIR=1: bf16 hi/lo out; PAIR=0: fp32 out.
// ===========================================================================
template <int PAIR>
__global__ void __launch_bounds__(256) layernorm_rows(
    const float* __restrict__ X, const float* __restrict__ w,
    const float* __restrict__ bb, float* __restrict__ Yf,
    __nv_bfloat16* __restrict__ Yhi, __nv_bfloat16* __restrict__ Ylo)
{
    const int row = blockIdx.x;
    const float* x = X + (size_t)row * DIM;
    const int tid = threadIdx.x;

    float v[4];
    float s = 0.0f;
#pragma unroll
    for (int i = 0; i < 4; i++) {
        v[i] = x[i * 256 + tid];
        s += v[i];
    }

    __shared__ float red[256];
    red[tid] = s;
    __syncthreads();
#pragma unroll
    for (int st = 128; st >= 1; st >>= 1) {
        if (tid < st) red[tid] += red[tid + st];
        __syncthreads();
    }
    float mu = red[0] * (1.0f / DIM);
    __syncthreads();

    float vs = 0.0f;
#pragma unroll
    for (int i = 0; i < 4; i++) {
        float d = v[i] - mu;
        vs += d * d;
    }
    red[tid] = vs;
    __syncthreads();
#pragma unroll
    for (int st = 128; st >= 1; st >>= 1) {
        if (tid < st) red[tid] += red[tid + st];
        __syncthreads();
    }
    float var = red[0] * (1.0f / DIM);
    float inv = rsqrtf(var + 1e-5f);

#pragma unroll
    for (int i = 0; i < 4; i++) {
        int c = i * 256 + tid;
        float y = (v[i] - mu) * inv * w[c] + bb[c];
        if (PAIR) {
            __nv_bfloat16 hi = __float2bfloat16(y);
            size_t o = (size_t)row * DIM + c;
            Yhi[o] = hi;
            Ylo[o] = __float2bfloat16(y - __bfloat162float(hi));
        } else {
            Yf[(size_t)row * DIM + c] = y;
        }
    }
}

// ===========================================================================
// Launch
// ===========================================================================
extern "C" void kernel_launch(void* const* d_in, const int* in_sizes, int n_in,
                              void* d_out, int out_size)
{
    const float* x     = (const float*)d_in[0];
    const float* qvk_w = (const float*)d_in[1];
    const float* qvk_b = (const float*)d_in[2];
    const float* qh_w  = (const float*)d_in[3];
    const float* qh_b  = (const float*)d_in[4];
    const float* kh_w  = (const float*)d_in[5];
    const float* kh_b  = (const float*)d_in[6];
    const float* vh_w  = (const float*)d_in[7];
    const float* vh_b  = (const float*)d_in[8];
    const float* o_w   = (const float*)d_in[9];
    const float* o_b   = (const float*)d_in[10];
    const float* ln1_w = (const float*)d_in[11];
    const float* ln1_b = (const float*)d_in[12];
    const float* m1_w  = (const float*)d_in[13];
    const float* m1_b  = (const float*)d_in[14];
    const float* m2_w  = (const float*)d_in[15];
    const float* m2_b  = (const float*)d_in[16];
    const float* ln2_w = (const float*)d_in[17];
    const float* ln2_b = (const float*)d_in[18];
    float* out = (float*)d_out;

    float *t1, *t3;
    __nv_bfloat16 *xhi, *xlo, *qvkhi, *qvklo, *atthi, *attlo,
                  *ln1hi, *ln1lo, *m1hi, *m1lo;
    __nv_bfloat16 *Qhi, *Qlo, *Khi, *Klo, *Vthi, *Vtlo;
    __nv_bfloat16 *wqvkhi, *wqvklo, *wqhi, *wqlo, *wkhi, *wklo,
                  *wvhi, *wvlo, *wohi, *wolo, *wm1hi, *wm1lo, *wm2hi, *wm2lo;

    cudaGetSymbolAddress((void**)&t1,  g_t1);
    cudaGetSymbolAddress((void**)&t3,  g_t3);
    cudaGetSymbolAddress((void**)&xhi, g_xhi);     cudaGetSymbolAddress((void**)&xlo, g_xlo);
    cudaGetSymbolAddress((void**)&qvkhi, g_qvkhi); cudaGetSymbolAddress((void**)&qvklo, g_qvklo);
    cudaGetSymbolAddress((void**)&atthi, g_atthi); cudaGetSymbolAddress((void**)&attlo, g_attlo);
    cudaGetSymbolAddress((void**)&ln1hi, g_ln1hi); cudaGetSymbolAddress((void**)&ln1lo, g_ln1lo);
    cudaGetSymbolAddress((void**)&m1hi, g_m1hi);   cudaGetSymbolAddress((void**)&m1lo, g_m1lo);
    cudaGetSymbolAddress((void**)&Qhi, g_Qhi);     cudaGetSymbolAddress((void**)&Qlo, g_Qlo);
    cudaGetSymbolAddress((void**)&Khi, g_Khi);     cudaGetSymbolAddress((void**)&Klo, g_Klo);
    cudaGetSymbolAddress((void**)&Vthi, g_Vthi);   cudaGetSymbolAddress((void**)&Vtlo, g_Vtlo);
    cudaGetSymbolAddress((void**)&wqvkhi, g_wqvkhi); cudaGetSymbolAddress((void**)&wqvklo, g_wqvklo);
    cudaGetSymbolAddress((void**)&wqhi, g_wqhi);   cudaGetSymbolAddress((void**)&wqlo, g_wqlo);
    cudaGetSymbolAddress((void**)&wkhi, g_wkhi);   cudaGetSymbolAddress((void**)&wklo, g_wklo);
    cudaGetSymbolAddress((void**)&wvhi, g_wvhi);   cudaGetSymbolAddress((void**)&wvlo, g_wvlo);
    cudaGetSymbolAddress((void**)&wohi, g_wohi);   cudaGetSymbolAddress((void**)&wolo, g_wolo);
    cudaGetSymbolAddress((void**)&wm1hi, g_wm1hi); cudaGetSymbolAddress((void**)&wm1lo, g_wm1lo);
    cudaGetSymbolAddress((void**)&wm2hi, g_wm2hi); cudaGetSymbolAddress((void**)&wm2lo, g_wm2lo);

    cudaFuncSetAttribute(gemm_mma,
                         cudaFuncAttributeMaxDynamicSharedMemorySize, GEMM_SMEM);
    cudaFuncSetAttribute(attn_mma,
                         cudaFuncAttributeMaxDynamicSharedMemorySize, ATTN_SMEM);

    const dim3 thr(256);
    const float inv8 = 1.0f / (sqrtf((float)DPH) + 1e-10f);

    // 0. batched transposes + input split (one launch)
    batched_pre<<<PRE_BLOCKS, thr>>>(
        qvk_w, qh_w, kh_w, vh_w, o_w, m1_w, m2_w, x,
        wqvkhi, wqvklo, wqhi, wqlo, wkhi, wklo, wvhi, wvlo,
        wohi, wolo, wm1hi, wm1lo, wm2hi, wm2lo, xhi, xlo);

    // 1. qvk projection -> bf16 pair
    gemm_mma<<<dim3(DH3 / BN, TTOK / BM), thr, GEMM_SMEM>>>(
        xhi, xlo, DIM, wqvkhi, wqvklo, qvk_b,
        nullptr, qvkhi, qvklo, DH3, DIM, OUT_PAIR);

    // 2. Q/K head projections -> [b][m][64]; V -> [b][dph][m]
    gemm_mma<<<dim3(DIM / BN, TTOK / BM), thr, GEMM_SMEM>>>(
        qvkhi,            qvklo,            DH3, wqhi, wqlo, qh_b,
        nullptr, Qhi, Qlo, 0, DIM, OUT_QKPAIR);
    gemm_mma<<<dim3(DIM / BN, TTOK / BM), thr, GEMM_SMEM>>>(
        qvkhi + DIM,      qvklo + DIM,      DH3, wkhi, wklo, kh_b,
        nullptr, Khi, Klo, 0, DIM, OUT_QKPAIR);
    gemm_mma<<<dim3(DIM / BN, TTOK / BM), thr, GEMM_SMEM>>>(
        qvkhi + 2 * DIM,  qvklo + 2 * DIM,  DH3, wvhi, wvlo, vh_b,
        nullptr, Vthi, Vtlo, 0, DIM, OUT_VT);

    // 3-5. Flash attention on tensor cores  (launch index 5 -> ncu target)
    attn_mma<<<dim3(MSEQ / 128, NB * NH), thr, ATTN_SMEM>>>(
        Qhi, Qlo, Khi, Klo, Vthi, Vtlo, atthi, attlo, inv8);

    // 6. O projection
    gemm_mma<<<dim3(DIM / BN, TTOK / BM), thr, GEMM_SMEM>>>(
        atthi, attlo, DIM, wohi, wolo, o_b,
        t1, nullptr, nullptr, DIM, DIM, OUT_F32);

    // 7. LN1 -> bf16 pair
    layernorm_rows<1><<<TTOK, thr>>>(t1, ln1_w, ln1_b, nullptr, ln1hi, ln1lo);

    // 8. m1 -> bf16 pair
    gemm_mma<<<dim3(DEXP / BN, TTOK / BM), thr, GEMM_SMEM>>>(
        ln1hi, ln1lo, DIM, wm1hi, wm1lo, m1_b,
        nullptr, m1hi, m1lo, DEXP, DIM, OUT_PAIR);

    // 9. m2 -> fp32
    gemm_mma<<<dim3(DIM / BN, TTOK / BM), thr, GEMM_SMEM>>>(
        m1hi, m1lo, DEXP, wm2hi, wm2lo, m2_b,
        t3, nullptr, nullptr, DIM, DEXP, OUT_F32);

    // 10. LN2 -> out
    layernorm_rows<0><<<TTOK, thr>>>(t3, ln2_w, ln2_b, out, nullptr, nullptr);
}